// round 7
// baseline (speedup 1.0000x reference)
#include <cuda_runtime.h>
#include <math.h>

#define NN 20000
#define EE 640000
#define DD 64
#define FULL 0xffffffffu
#define PBLK 148          // persistent prep grid (all co-resident on 148 SMs)

// ---------------- scratch ----------------
__device__ __align__(16) float g_deg[NN];      // sum of incoming ew (+1 self-loop at use)
__device__ __align__(16) int   g_cnt[NN];
__device__ __align__(16) int   g_off[NN + 1];
__device__ __align__(16) int   g_bsum[PBLK];
__device__ __align__(16) int   g_boff[PBLK];
__device__ __align__(16) int   g_rank[EE];
__device__ __align__(16) int   g_src[EE];
__device__ __align__(16) int   g_dst[EE];
__device__ __align__(16) int2  g_csr[EE];
__device__ __align__(16) float g_h1[NN * DD];
__device__ __align__(16) float g_h2[NN * DD];
__device__ int g_is64;
__device__ int g_barcnt = 0;
__device__ int g_barflag = 0;   // monotonic generation (never reset -> graph-replay safe)

__device__ __forceinline__ float selu_f(float x) {
    const float sc = 1.0507009873554805f;
    const float al = 1.6732632423543772f;
    return x > 0.f ? sc * x : sc * al * (expf(x) - 1.f);
}

// ---------------- software grid barrier (all PBLK blocks resident) ----------------
__device__ __forceinline__ void gridbar(int target) {
    __syncthreads();
    if (threadIdx.x == 0) {
        __threadfence();
        int t = atomicAdd(&g_barcnt, 1);
        if (t == PBLK - 1) {
            g_barcnt = 0;
            atomicExch(&g_barflag, target);
        } else {
            while (atomicAdd(&g_barflag, 0) < target) {}
        }
    }
    __syncthreads();
}

// ---------------- block exclusive-scan helper (256 threads) ----------------
__device__ __forceinline__ int block_excl_scan_256(int v, int* total_out) {
    __shared__ int wsum[8];
    int lane = threadIdx.x & 31, wid = threadIdx.x >> 5;
    int inc = v;
    #pragma unroll
    for (int o = 1; o < 32; o <<= 1) {
        int u = __shfl_up_sync(FULL, inc, o);
        if (lane >= o) inc += u;
    }
    if (lane == 31) wsum[wid] = inc;
    __syncthreads();
    if (wid == 0) {
        int w = (lane < 8) ? wsum[lane] : 0;
        #pragma unroll
        for (int o = 1; o < 8; o <<= 1) {
            int u = __shfl_up_sync(FULL, w, o);
            if (lane >= o) w += u;
        }
        if (lane < 8) wsum[lane] = w;
    }
    __syncthreads();
    int base = (wid > 0) ? wsum[wid - 1] : 0;
    if (total_out) *total_out = wsum[7];
    return base + inc - v;
}

// ---------------- ONE fused prep kernel: zero -> edges -> scan -> CSR fill ----------------
__global__ __launch_bounds__(256) void prep_fused_kernel(const int* __restrict__ ei32,
                                                         const float* __restrict__ ew) {
    const int tid = threadIdx.x, bid = blockIdx.x;
    const int gt = bid * 256 + tid;
    const int gs = PBLK * 256;
    const int gen0 = atomicAdd(&g_barflag, 0);  // snapshot (stable until first release)

    // phase 0: zero counters + dtype probe
    for (int i = gt; i < NN; i += gs) { g_cnt[i] = 0; g_deg[i] = 0.f; }
    if (gt == 0) {
        int flag = 1;
        #pragma unroll
        for (int i = 0; i < 64; i++)
            if (ei32[2 * i + 1] != 0) flag = 0;
        g_is64 = flag;
    }
    gridbar(gen0 + 1);

    // phase 1: edge extraction + degree + per-dst rank
    const int is64 = g_is64;
    for (int e = gt; e < EE; e += gs) {
        int s, d;
        if (is64) { s = ei32[2 * e]; d = ei32[2 * (EE + e)]; }
        else      { s = ei32[e];     d = ei32[EE + e]; }
        g_src[e] = s;
        g_dst[e] = d;
        atomicAdd(&g_deg[d], ew[e]);
        g_rank[e] = atomicAdd(&g_cnt[d], 1);
    }
    gridbar(gen0 + 2);

    // phase 2a: per-block partial sums of g_cnt (chunk of CH nodes per block)
    const int CH = (NN + PBLK - 1) / PBLK;  // 136
    const int lo = bid * CH;
    int myi = lo + tid;
    int v = (tid < CH && myi < NN) ? g_cnt[myi] : 0;
    {
        int r = v, lane = tid & 31, wid = tid >> 5;
        __shared__ int ws[8];
        #pragma unroll
        for (int o = 16; o; o >>= 1) r += __shfl_xor_sync(FULL, r, o);
        if (lane == 0) ws[wid] = r;
        __syncthreads();
        if (tid == 0) {
            int s = 0;
            #pragma unroll
            for (int w = 0; w < 8; w++) s += ws[w];
            g_bsum[bid] = s;
        }
    }
    gridbar(gen0 + 3);

    // phase 2b: block 0 scans the PBLK partials
    if (bid == 0) {
        int v2 = (tid < PBLK) ? g_bsum[tid] : 0;
        int tot;
        int ex = block_excl_scan_256(v2, &tot);
        if (tid < PBLK) g_boff[tid] = ex;
        if (tid == 0) g_off[NN] = tot;
    }
    gridbar(gen0 + 4);

    // phase 2c: local exclusive scan -> global offsets
    int excl = block_excl_scan_256(v, nullptr);
    if (tid < CH && myi < NN) g_off[myi] = excl + g_boff[bid];
    gridbar(gen0 + 5);

    // phase 3: norm + CSR placement
    for (int e = gt; e < EE; e += gs) {
        int s = g_src[e], d = g_dst[e];
        float nrm = rsqrtf(1.f + g_deg[s]) * ew[e] * rsqrtf(1.f + g_deg[d]);
        g_csr[g_off[d] + g_rank[e]] = make_int2(s, __float_as_int(nrm));
    }
}

// --------- warp-cooperative CSR gather: float2 per lane ---------
__device__ __forceinline__ float2 gather_col2(const float* __restrict__ hsrc,
                                              int n, int lane) {
    int start = g_off[n], end = g_off[n + 1];
    float2 hv = *reinterpret_cast<const float2*>(&hsrc[(size_t)n * DD + lane * 2]);
    float inv = 1.0f / (1.f + g_deg[n]);
    float ax = hv.x * inv, ay = hv.y * inv;
    for (int base = start; base < end; base += 32) {
        int idx = base + lane;
        int2 ed = (idx < end) ? g_csr[idx] : make_int2(0, 0);
        int cnt = min(32, end - base);
        int k = 0;
        for (; k + 4 <= cnt; k += 4) {
            int   sa = __shfl_sync(FULL, ed.x, k);
            float wa = __int_as_float(__shfl_sync(FULL, ed.y, k));
            int   sb = __shfl_sync(FULL, ed.x, k + 1);
            float wb = __int_as_float(__shfl_sync(FULL, ed.y, k + 1));
            int   sc = __shfl_sync(FULL, ed.x, k + 2);
            float wc = __int_as_float(__shfl_sync(FULL, ed.y, k + 2));
            int   sd = __shfl_sync(FULL, ed.x, k + 3);
            float wd = __int_as_float(__shfl_sync(FULL, ed.y, k + 3));
            float2 va = *reinterpret_cast<const float2*>(&hsrc[(size_t)sa * DD + lane * 2]);
            float2 vb = *reinterpret_cast<const float2*>(&hsrc[(size_t)sb * DD + lane * 2]);
            float2 vc = *reinterpret_cast<const float2*>(&hsrc[(size_t)sc * DD + lane * 2]);
            float2 vd = *reinterpret_cast<const float2*>(&hsrc[(size_t)sd * DD + lane * 2]);
            ax += wa * va.x + wb * vb.x;
            ay += wa * va.y + wb * vb.y;
            ax += wc * vc.x + wd * vd.x;
            ay += wc * vc.y + wd * vd.y;
        }
        for (; k < cnt; k++) {
            int   sa = __shfl_sync(FULL, ed.x, k);
            float wa = __int_as_float(__shfl_sync(FULL, ed.y, k));
            float2 va = *reinterpret_cast<const float2*>(&hsrc[(size_t)sa * DD + lane * 2]);
            ax += wa * va.x; ay += wa * va.y;
        }
    }
    return make_float2(ax, ay);
}

// --------- warp matvec: y = xs @ W (row-major 64x64), float4 streaming ---------
__device__ __forceinline__ void warp_matvec_g(const float* __restrict__ Wn,
                                              const float* xs, int lane, float acc[4]) {
    acc[0] = acc[1] = acc[2] = acc[3] = 0.f;
    int half = lane >> 4;
    int coff = (lane & 15) * 4;
    #pragma unroll
    for (int d = 0; d < DD; d += 2) {
        float4 w4 = *reinterpret_cast<const float4*>(&Wn[(d + half) * DD + coff]);
        float xv = xs[d + half];
        acc[0] += xv * w4.x; acc[1] += xv * w4.y;
        acc[2] += xv * w4.z; acc[3] += xv * w4.w;
    }
    #pragma unroll
    for (int c = 0; c < 4; c++)
        acc[c] += __shfl_xor_sync(FULL, acc[c], 16);
}

// ---------------- conv1 lin: h1 = x @ Wc1 ----------------
__global__ __launch_bounds__(256) void gemm1_kernel(const float* __restrict__ x,
                                                    const float* __restrict__ Wc) {
    __shared__ float Ws[DD * DD];
    __shared__ float xs[8][DD];
    int tid = threadIdx.x;
    #pragma unroll
    for (int i = tid; i < DD * DD; i += 256) Ws[i] = Wc[i];
    int w = tid >> 5, lane = tid & 31;
    int node = blockIdx.x * 8 + w;
    *reinterpret_cast<float2*>(&xs[w][lane * 2]) =
        *reinterpret_cast<const float2*>(&x[(size_t)node * DD + lane * 2]);
    __syncthreads();
    float acc[4];
    warp_matvec_g(Ws, xs[w], lane, acc);
    if (lane < 16) {
        float4 o = make_float4(acc[0], acc[1], acc[2], acc[3]);
        *reinterpret_cast<float4*>(&g_h1[(size_t)node * DD + (lane & 15) * 4]) = o;
    }
}

// ---------------- conv2 fused: gather(h1) -> selu(+bc1) -> @Wc2 -> h2 ----------------
__global__ __launch_bounds__(256) void conv2_fused_kernel(const float* __restrict__ Wc,
                                                          const float* __restrict__ bin) {
    __shared__ float Ws[DD * DD];
    __shared__ float xs[8][DD];
    int tid = threadIdx.x;
    #pragma unroll
    for (int i = tid; i < DD * DD; i += 256) Ws[i] = Wc[i];
    int w = tid >> 5, lane = tid & 31;
    int node = blockIdx.x * 8 + w;
    float2 acc2 = gather_col2(g_h1, node, lane);
    xs[w][lane * 2]     = selu_f(acc2.x + bin[lane * 2]);
    xs[w][lane * 2 + 1] = selu_f(acc2.y + bin[lane * 2 + 1]);
    __syncthreads();
    float acc[4];
    warp_matvec_g(Ws, xs[w], lane, acc);
    if (lane < 16) {
        float4 o = make_float4(acc[0], acc[1], acc[2], acc[3]);
        *reinterpret_cast<float4*>(&g_h2[(size_t)node * DD + (lane & 15) * 4]) = o;
    }
}

// ------- final fused: gather(h2) -> selu(+bc2) -> W1 -> LN -> W2 -> out -------
__global__ __launch_bounds__(256) void final_fused_kernel(
        const float* __restrict__ bc2,
        const float* __restrict__ W1, const float* __restrict__ b1,
        const float* __restrict__ W2, const float* __restrict__ b2,
        const float* __restrict__ gam, const float* __restrict__ bet,
        float* __restrict__ out) {
    __shared__ float hs[8][DD];
    __shared__ float ts[8][DD];
    int tid = threadIdx.x;
    int w = tid >> 5, lane = tid & 31;
    int node = blockIdx.x * 8 + w;
    int coff = (lane & 15) * 4;

    float2 acc2 = gather_col2(g_h2, node, lane);
    hs[w][lane * 2]     = selu_f(acc2.x + bc2[lane * 2]);
    hs[w][lane * 2 + 1] = selu_f(acc2.y + bc2[lane * 2 + 1]);
    __syncwarp();

    const float* W1n = W1 + (size_t)node * (DD * DD);
    float v[4];
    warp_matvec_g(W1n, hs[w], lane, v);
    float4 b1v = *reinterpret_cast<const float4*>(&b1[(size_t)node * DD + coff]);
    v[0] += b1v.x; v[1] += b1v.y; v[2] += b1v.z; v[3] += b1v.w;

    float s1 = v[0] + v[1] + v[2] + v[3];
    float s2 = v[0] * v[0] + v[1] * v[1] + v[2] * v[2] + v[3] * v[3];
    #pragma unroll
    for (int o = 8; o; o >>= 1) {
        s1 += __shfl_xor_sync(FULL, s1, o);
        s2 += __shfl_xor_sync(FULL, s2, o);
    }
    float mu  = s1 * (1.f / DD);
    float var = s2 * (1.f / DD) - mu * mu;
    float rstd = rsqrtf(var + 1e-5f);
    float4 gv = *reinterpret_cast<const float4*>(&gam[coff]);
    float4 bv = *reinterpret_cast<const float4*>(&bet[coff]);
    float t0 = (v[0] - mu) * rstd * gv.x + bv.x;
    float t1 = (v[1] - mu) * rstd * gv.y + bv.y;
    float t2 = (v[2] - mu) * rstd * gv.z + bv.z;
    float t3 = (v[3] - mu) * rstd * gv.w + bv.w;
    if (lane < 16)
        *reinterpret_cast<float4*>(&ts[w][coff]) = make_float4(t0, t1, t2, t3);
    __syncwarp();

    const float* W2n = W2 + (size_t)node * (DD * DD);
    float q[4];
    warp_matvec_g(W2n, ts[w], lane, q);
    if (lane < 16) {
        float4 b2v = *reinterpret_cast<const float4*>(&b2[(size_t)node * DD + coff]);
        float4 o = make_float4(q[0] + b2v.x, q[1] + b2v.y, q[2] + b2v.z, q[3] + b2v.w);
        *reinterpret_cast<float4*>(&out[(size_t)node * DD + coff]) = o;
    }
}

// ---------------- launch ----------------
extern "C" void kernel_launch(void* const* d_in, const int* in_sizes, int n_in,
                              void* d_out, int out_size) {
    const float* x   = (const float*)d_in[0];
    const int*   ei  = (const int*)d_in[1];
    const float* ew  = (const float*)d_in[2];
    const float* Wc1 = (const float*)d_in[3];
    const float* bc1 = (const float*)d_in[4];
    const float* Wc2 = (const float*)d_in[5];
    const float* bc2 = (const float*)d_in[6];
    const float* W1  = (const float*)d_in[7];
    const float* b1  = (const float*)d_in[8];
    const float* W2  = (const float*)d_in[9];
    const float* b2  = (const float*)d_in[10];
    const float* gam = (const float*)d_in[11];
    const float* bet = (const float*)d_in[12];
    float* out = (float*)d_out;

    static cudaStream_t s2 = 0;
    static cudaEvent_t evF = 0, evJ = 0;
    static int ready = 0;
    if (!ready) {
        bool ok = cudaStreamCreateWithFlags(&s2, cudaStreamNonBlocking) == cudaSuccess &&
                  cudaEventCreateWithFlags(&evF, cudaEventDisableTiming) == cudaSuccess &&
                  cudaEventCreateWithFlags(&evJ, cudaEventDisableTiming) == cudaSuccess;
        ready = ok ? 1 : -1;
    }

    bool fork = (ready == 1);
    if (fork) {
        cudaEventRecord(evF, 0);
        cudaStreamWaitEvent(s2, evF, 0);
        gemm1_kernel<<<NN / 8, 256, 0, s2>>>(x, Wc1);  // overlaps with prep
        cudaEventRecord(evJ, s2);
    }

    prep_fused_kernel<<<PBLK, 256>>>(ei, ew);

    if (fork)
        cudaStreamWaitEvent(0, evJ, 0);
    else
        gemm1_kernel<<<NN / 8, 256>>>(x, Wc1);

    conv2_fused_kernel<<<NN / 8, 256>>>(Wc2, bc1);
    final_fused_kernel<<<NN / 8, 256>>>(bc2, W1, b1, W2, b2, gam, bet, out);
}

// round 8
// speedup vs baseline: 1.2101x; 1.2101x over previous
#include <cuda_runtime.h>
#include <math.h>

#define NN 20000
#define EE 640000
#define DD 64
#define FULL 0xffffffffu
#define NBLK 79   // ceil(NN/256)

// ---------------- scratch ----------------
// g_cnt / g_deg are zero at every kernel_launch entry: statically zero-initialized,
// and scanC_kernel re-zeroes them after their last use within each invocation.
__device__ __align__(16) float g_deg[NN];
__device__ __align__(16) int   g_cnt[NN];
__device__ __align__(16) float g_dinv[NN];     // rsqrt(1+deg)
__device__ __align__(16) float g_inv[NN];      // 1/(1+deg)
__device__ __align__(16) int   g_off[NN + 1];
__device__ __align__(16) int   g_bsum[NBLK];
__device__ __align__(16) int   g_boff[NBLK];
__device__ __align__(16) int   g_rank[EE];
__device__ __align__(16) int   g_src[EE];
__device__ __align__(16) int   g_dst[EE];
__device__ __align__(16) int2  g_csr[EE];
__device__ __align__(16) float g_h1[NN * DD];
__device__ __align__(16) float g_h2[NN * DD];

__device__ __forceinline__ float selu_f(float x) {
    const float sc = 1.0507009873554805f;
    const float al = 1.6732632423543772f;
    return x > 0.f ? sc * x : sc * al * (expf(x) - 1.f);
}

// ---------------- edge extraction + degree + per-dst rank (probe inlined) ----------------
__global__ __launch_bounds__(256) void edge_prep_kernel(const int* __restrict__ ei32,
                                                        const float* __restrict__ ew) {
    __shared__ int s_is64;
    int tid = threadIdx.x;
    if (tid < 32) {
        // lanes check high words of first 64 int64 slots (ids < 20000 -> all zero iff int64)
        int ok = (ei32[2 * tid + 1] == 0) && (ei32[2 * (tid + 32) + 1] == 0);
        unsigned m = __ballot_sync(FULL, ok);
        if (tid == 0) s_is64 = (m == FULL);
    }
    __syncthreads();
    int is64 = s_is64;
    int e = blockIdx.x * 256 + tid;
    if (e >= EE) return;
    int s, d;
    if (is64) { s = ei32[2 * e]; d = ei32[2 * (EE + e)]; }
    else      { s = ei32[e];     d = ei32[EE + e]; }
    g_src[e] = s;
    g_dst[e] = d;
    atomicAdd(&g_deg[d], ew[e]);
    g_rank[e] = atomicAdd(&g_cnt[d], 1);
}

// ---------------- scanA: per-block sums of g_cnt ----------------
__global__ __launch_bounds__(256) void scanA_kernel() {
    int i = blockIdx.x * 256 + threadIdx.x;
    int v = (i < NN) ? g_cnt[i] : 0;
    __shared__ int wsum[8];
    int lane = threadIdx.x & 31, wid = threadIdx.x >> 5;
    #pragma unroll
    for (int o = 16; o; o >>= 1) v += __shfl_xor_sync(FULL, v, o);
    if (lane == 0) wsum[wid] = v;
    __syncthreads();
    if (threadIdx.x == 0) {
        int s = 0;
        #pragma unroll
        for (int w = 0; w < 8; w++) s += wsum[w];
        g_bsum[blockIdx.x] = s;
    }
}

// ---------------- scanB: scan NBLK block sums ----------------
__global__ void scanB_kernel() {
    __shared__ int buf[NBLK];
    int t = threadIdx.x;
    if (t < NBLK) buf[t] = g_bsum[t];
    __syncthreads();
    if (t == 0) {
        int run = 0;
        for (int i = 0; i < NBLK; i++) {
            int c = buf[i];
            buf[i] = run;
            run += c;
        }
        g_off[NN] = run;
    }
    __syncthreads();
    if (t < NBLK) g_boff[t] = buf[t];
}

// ------- scanC: local scan -> g_off; per-node dinv/inv; self-restore cnt/deg to zero -------
__global__ __launch_bounds__(256) void scanC_kernel() {
    int i = blockIdx.x * 256 + threadIdx.x;
    int v = (i < NN) ? g_cnt[i] : 0;
    // block exclusive scan
    __shared__ int wsum[8];
    int lane = threadIdx.x & 31, wid = threadIdx.x >> 5;
    int inc = v;
    #pragma unroll
    for (int o = 1; o < 32; o <<= 1) {
        int u = __shfl_up_sync(FULL, inc, o);
        if (lane >= o) inc += u;
    }
    if (lane == 31) wsum[wid] = inc;
    __syncthreads();
    if (wid == 0) {
        int w = (lane < 8) ? wsum[lane] : 0;
        #pragma unroll
        for (int o = 1; o < 8; o <<= 1) {
            int u = __shfl_up_sync(FULL, w, o);
            if (lane >= o) w += u;
        }
        if (lane < 8) wsum[lane] = w;
    }
    __syncthreads();
    int excl = (wid > 0 ? wsum[wid - 1] : 0) + inc - v;
    if (i < NN) {
        g_off[i] = excl + g_boff[blockIdx.x];
        float dp1 = 1.f + g_deg[i];
        g_dinv[i] = rsqrtf(dp1);
        g_inv[i]  = 1.f / dp1;
        g_cnt[i] = 0;     // restore for next replay
        g_deg[i] = 0.f;   // restore for next replay
    }
}

// ---------------- norm + CSR placement (2 edges/thread) ----------------
__global__ __launch_bounds__(256) void norm_fill_kernel(const float* __restrict__ ew) {
    int e0 = blockIdx.x * blockDim.x + threadIdx.x;
    int e1 = e0 + EE / 2;
    if (e0 >= EE / 2) return;
    int s0 = g_src[e0], d0 = g_dst[e0];
    int s1 = g_src[e1], d1 = g_dst[e1];
    float n0 = g_dinv[s0] * ew[e0] * g_dinv[d0];
    float n1 = g_dinv[s1] * ew[e1] * g_dinv[d1];
    int p0 = g_off[d0] + g_rank[e0];
    int p1 = g_off[d1] + g_rank[e1];
    g_csr[p0] = make_int2(s0, __float_as_int(n0));
    g_csr[p1] = make_int2(s1, __float_as_int(n1));
}

// --------- warp-cooperative CSR gather: float2 per lane ---------
__device__ __forceinline__ float2 gather_col2(const float* __restrict__ hsrc,
                                              int n, int lane) {
    int start = g_off[n], end = g_off[n + 1];
    float2 hv = *reinterpret_cast<const float2*>(&hsrc[(size_t)n * DD + lane * 2]);
    float inv = g_inv[n];
    float ax = hv.x * inv, ay = hv.y * inv;
    for (int base = start; base < end; base += 32) {
        int idx = base + lane;
        int2 ed = (idx < end) ? g_csr[idx] : make_int2(0, 0);
        int cnt = min(32, end - base);
        int k = 0;
        for (; k + 4 <= cnt; k += 4) {
            int   sa = __shfl_sync(FULL, ed.x, k);
            float wa = __int_as_float(__shfl_sync(FULL, ed.y, k));
            int   sb = __shfl_sync(FULL, ed.x, k + 1);
            float wb = __int_as_float(__shfl_sync(FULL, ed.y, k + 1));
            int   sc = __shfl_sync(FULL, ed.x, k + 2);
            float wc = __int_as_float(__shfl_sync(FULL, ed.y, k + 2));
            int   sd = __shfl_sync(FULL, ed.x, k + 3);
            float wd = __int_as_float(__shfl_sync(FULL, ed.y, k + 3));
            float2 va = *reinterpret_cast<const float2*>(&hsrc[(size_t)sa * DD + lane * 2]);
            float2 vb = *reinterpret_cast<const float2*>(&hsrc[(size_t)sb * DD + lane * 2]);
            float2 vc = *reinterpret_cast<const float2*>(&hsrc[(size_t)sc * DD + lane * 2]);
            float2 vd = *reinterpret_cast<const float2*>(&hsrc[(size_t)sd * DD + lane * 2]);
            ax += wa * va.x + wb * vb.x;
            ay += wa * va.y + wb * vb.y;
            ax += wc * vc.x + wd * vd.x;
            ay += wc * vc.y + wd * vd.y;
        }
        for (; k < cnt; k++) {
            int   sa = __shfl_sync(FULL, ed.x, k);
            float wa = __int_as_float(__shfl_sync(FULL, ed.y, k));
            float2 va = *reinterpret_cast<const float2*>(&hsrc[(size_t)sa * DD + lane * 2]);
            ax += wa * va.x; ay += wa * va.y;
        }
    }
    return make_float2(ax, ay);
}

// --------- warp matvec: y = xs @ W (row-major 64x64), float4 streaming ---------
__device__ __forceinline__ void warp_matvec_g(const float* __restrict__ Wn,
                                              const float* xs, int lane, float acc[4]) {
    acc[0] = acc[1] = acc[2] = acc[3] = 0.f;
    int half = lane >> 4;
    int coff = (lane & 15) * 4;
    #pragma unroll
    for (int d = 0; d < DD; d += 2) {
        float4 w4 = *reinterpret_cast<const float4*>(&Wn[(d + half) * DD + coff]);
        float xv = xs[d + half];
        acc[0] += xv * w4.x; acc[1] += xv * w4.y;
        acc[2] += xv * w4.z; acc[3] += xv * w4.w;
    }
    #pragma unroll
    for (int c = 0; c < 4; c++)
        acc[c] += __shfl_xor_sync(FULL, acc[c], 16);
}

// ---------------- conv1 lin: h1 = x @ Wc1 ----------------
__global__ __launch_bounds__(256) void gemm1_kernel(const float* __restrict__ x,
                                                    const float* __restrict__ Wc) {
    __shared__ float Ws[DD * DD];
    __shared__ float xs[8][DD];
    int tid = threadIdx.x;
    #pragma unroll
    for (int i = tid; i < DD * DD; i += 256) Ws[i] = Wc[i];
    int w = tid >> 5, lane = tid & 31;
    int node = blockIdx.x * 8 + w;
    *reinterpret_cast<float2*>(&xs[w][lane * 2]) =
        *reinterpret_cast<const float2*>(&x[(size_t)node * DD + lane * 2]);
    __syncthreads();
    float acc[4];
    warp_matvec_g(Ws, xs[w], lane, acc);
    if (lane < 16) {
        float4 o = make_float4(acc[0], acc[1], acc[2], acc[3]);
        *reinterpret_cast<float4*>(&g_h1[(size_t)node * DD + (lane & 15) * 4]) = o;
    }
}

// ---------------- conv2 fused: gather(h1) -> selu(+bc1) -> @Wc2 -> h2 ----------------
__global__ __launch_bounds__(256) void conv2_fused_kernel(const float* __restrict__ Wc,
                                                          const float* __restrict__ bin) {
    __shared__ float Ws[DD * DD];
    __shared__ float xs[8][DD];
    int tid = threadIdx.x;
    #pragma unroll
    for (int i = tid; i < DD * DD; i += 256) Ws[i] = Wc[i];
    int w = tid >> 5, lane = tid & 31;
    int node = blockIdx.x * 8 + w;
    float2 acc2 = gather_col2(g_h1, node, lane);
    xs[w][lane * 2]     = selu_f(acc2.x + bin[lane * 2]);
    xs[w][lane * 2 + 1] = selu_f(acc2.y + bin[lane * 2 + 1]);
    __syncthreads();
    float acc[4];
    warp_matvec_g(Ws, xs[w], lane, acc);
    if (lane < 16) {
        float4 o = make_float4(acc[0], acc[1], acc[2], acc[3]);
        *reinterpret_cast<float4*>(&g_h2[(size_t)node * DD + (lane & 15) * 4]) = o;
    }
}

// ------- final fused: gather(h2) -> selu(+bc2) -> W1 -> LN -> W2 -> out -------
__global__ __launch_bounds__(256) void final_fused_kernel(
        const float* __restrict__ bc2,
        const float* __restrict__ W1, const float* __restrict__ b1,
        const float* __restrict__ W2, const float* __restrict__ b2,
        const float* __restrict__ gam, const float* __restrict__ bet,
        float* __restrict__ out) {
    __shared__ float hs[8][DD];
    __shared__ float ts[8][DD];
    int tid = threadIdx.x;
    int w = tid >> 5, lane = tid & 31;
    int node = blockIdx.x * 8 + w;
    int coff = (lane & 15) * 4;

    float2 acc2 = gather_col2(g_h2, node, lane);
    hs[w][lane * 2]     = selu_f(acc2.x + bc2[lane * 2]);
    hs[w][lane * 2 + 1] = selu_f(acc2.y + bc2[lane * 2 + 1]);
    __syncwarp();

    const float* W1n = W1 + (size_t)node * (DD * DD);
    float v[4];
    warp_matvec_g(W1n, hs[w], lane, v);
    float4 b1v = *reinterpret_cast<const float4*>(&b1[(size_t)node * DD + coff]);
    v[0] += b1v.x; v[1] += b1v.y; v[2] += b1v.z; v[3] += b1v.w;

    float s1 = v[0] + v[1] + v[2] + v[3];
    float s2 = v[0] * v[0] + v[1] * v[1] + v[2] * v[2] + v[3] * v[3];
    #pragma unroll
    for (int o = 8; o; o >>= 1) {
        s1 += __shfl_xor_sync(FULL, s1, o);
        s2 += __shfl_xor_sync(FULL, s2, o);
    }
    float mu  = s1 * (1.f / DD);
    float var = s2 * (1.f / DD) - mu * mu;
    float rstd = rsqrtf(var + 1e-5f);
    float4 gv = *reinterpret_cast<const float4*>(&gam[coff]);
    float4 bv = *reinterpret_cast<const float4*>(&bet[coff]);
    float t0 = (v[0] - mu) * rstd * gv.x + bv.x;
    float t1 = (v[1] - mu) * rstd * gv.y + bv.y;
    float t2 = (v[2] - mu) * rstd * gv.z + bv.z;
    float t3 = (v[3] - mu) * rstd * gv.w + bv.w;
    if (lane < 16)
        *reinterpret_cast<float4*>(&ts[w][coff]) = make_float4(t0, t1, t2, t3);
    __syncwarp();

    const float* W2n = W2 + (size_t)node * (DD * DD);
    float q[4];
    warp_matvec_g(W2n, ts[w], lane, q);
    if (lane < 16) {
        float4 b2v = *reinterpret_cast<const float4*>(&b2[(size_t)node * DD + coff]);
        float4 o = make_float4(q[0] + b2v.x, q[1] + b2v.y, q[2] + b2v.z, q[3] + b2v.w);
        *reinterpret_cast<float4*>(&out[(size_t)node * DD + coff]) = o;
    }
}

// ---------------- launch ----------------
extern "C" void kernel_launch(void* const* d_in, const int* in_sizes, int n_in,
                              void* d_out, int out_size) {
    const float* x   = (const float*)d_in[0];
    const int*   ei  = (const int*)d_in[1];
    const float* ew  = (const float*)d_in[2];
    const float* Wc1 = (const float*)d_in[3];
    const float* bc1 = (const float*)d_in[4];
    const float* Wc2 = (const float*)d_in[5];
    const float* bc2 = (const float*)d_in[6];
    const float* W1  = (const float*)d_in[7];
    const float* b1  = (const float*)d_in[8];
    const float* W2  = (const float*)d_in[9];
    const float* b2  = (const float*)d_in[10];
    const float* gam = (const float*)d_in[11];
    const float* bet = (const float*)d_in[12];
    float* out = (float*)d_out;

    static cudaStream_t s2 = 0;
    static cudaEvent_t evF = 0, evJ = 0;
    static int ready = 0;
    if (!ready) {
        bool ok = cudaStreamCreateWithFlags(&s2, cudaStreamNonBlocking) == cudaSuccess &&
                  cudaEventCreateWithFlags(&evF, cudaEventDisableTiming) == cudaSuccess &&
                  cudaEventCreateWithFlags(&evJ, cudaEventDisableTiming) == cudaSuccess;
        ready = ok ? 1 : -1;
    }

    bool fork = (ready == 1);
    if (fork) {
        cudaEventRecord(evF, 0);
        cudaStreamWaitEvent(s2, evF, 0);
        gemm1_kernel<<<NN / 8, 256, 0, s2>>>(x, Wc1);  // overlaps with prep chain
        cudaEventRecord(evJ, s2);
    }

    edge_prep_kernel<<<EE / 256, 256>>>(ei, ew);
    scanA_kernel<<<NBLK, 256>>>();
    scanB_kernel<<<1, 128>>>();
    scanC_kernel<<<NBLK, 256>>>();
    norm_fill_kernel<<<EE / 512, 256>>>(ew);

    if (fork)
        cudaStreamWaitEvent(0, evJ, 0);
    else
        gemm1_kernel<<<NN / 8, 256>>>(x, Wc1);

    conv2_fused_kernel<<<NN / 8, 256>>>(Wc2, bc1);
    final_fused_kernel<<<NN / 8, 256>>>(bc2, W1, b1, W2, b2, gam, bet, out);
}

// round 9
// speedup vs baseline: 1.2541x; 1.0364x over previous
#include <cuda_runtime.h>
#include <math.h>

#define NN 20000
#define EE 640000
#define DD 64
#define CAP 128          // ELL capacity per dst node (mean in-degree 32; P(>128) ~ 0)
#define FULL 0xffffffffu

// ---------------- scratch ----------------
// g_cnt / g_deg are zero at every kernel_launch entry: statically zero-initialized,
// and final_fused_kernel re-zeroes them after their last use within each invocation.
__device__ __align__(16) float g_deg[NN];
__device__ __align__(16) int   g_cnt[NN];
__device__ __align__(16) int   g_rank[EE];
__device__ __align__(16) int   g_src[EE];
__device__ __align__(16) int   g_dst[EE];
__device__ __align__(16) int2  g_ell[NN * CAP];   // (src, norm-bits), slot = dst*CAP + rank
__device__ __align__(16) float g_h1[NN * DD];
__device__ __align__(16) float g_h2[NN * DD];

__device__ __forceinline__ float selu_f(float x) {
    const float sc = 1.0507009873554805f;
    const float al = 1.6732632423543772f;
    return x > 0.f ? sc * x : sc * al * (expf(x) - 1.f);
}

// ---------------- edge extraction + degree + per-dst rank (dtype probe inlined) ----------------
__global__ __launch_bounds__(256) void edge_prep_kernel(const int* __restrict__ ei32,
                                                        const float* __restrict__ ew) {
    __shared__ int s_is64;
    int tid = threadIdx.x;
    if (tid < 32) {
        int ok = (ei32[2 * tid + 1] == 0) && (ei32[2 * (tid + 32) + 1] == 0);
        unsigned m = __ballot_sync(FULL, ok);
        if (tid == 0) s_is64 = (m == FULL);
    }
    __syncthreads();
    int is64 = s_is64;
    int e = blockIdx.x * 256 + tid;
    if (e >= EE) return;
    int s, d;
    if (is64) { s = ei32[2 * e]; d = ei32[2 * (EE + e)]; }
    else      { s = ei32[e];     d = ei32[EE + e]; }
    g_src[e] = s;
    g_dst[e] = d;
    atomicAdd(&g_deg[d], ew[e]);
    g_rank[e] = atomicAdd(&g_cnt[d], 1);
}

// ---------------- norm + ELL placement (2 edges/thread, no scan needed) ----------------
__global__ __launch_bounds__(256) void norm_fill_kernel(const float* __restrict__ ew) {
    int e0 = blockIdx.x * blockDim.x + threadIdx.x;
    int e1 = e0 + EE / 2;
    if (e0 >= EE / 2) return;
    int s0 = g_src[e0], d0 = g_dst[e0];
    int s1 = g_src[e1], d1 = g_dst[e1];
    float n0 = rsqrtf(1.f + g_deg[s0]) * ew[e0] * rsqrtf(1.f + g_deg[d0]);
    float n1 = rsqrtf(1.f + g_deg[s1]) * ew[e1] * rsqrtf(1.f + g_deg[d1]);
    g_ell[d0 * CAP + g_rank[e0]] = make_int2(s0, __float_as_int(n0));
    g_ell[d1 * CAP + g_rank[e1]] = make_int2(s1, __float_as_int(n1));
}

// --------- warp-cooperative ELL gather: float2 per lane ---------
__device__ __forceinline__ float2 gather_col2(const float* __restrict__ hsrc,
                                              int n, int lane) {
    int cnt_all = g_cnt[n];
    const int2* row = &g_ell[(size_t)n * CAP];
    float2 hv = *reinterpret_cast<const float2*>(&hsrc[(size_t)n * DD + lane * 2]);
    float inv = 1.f / (1.f + g_deg[n]);
    float ax = hv.x * inv, ay = hv.y * inv;
    for (int base = 0; base < cnt_all; base += 32) {
        int idx = base + lane;
        int2 ed = (idx < cnt_all) ? row[idx] : make_int2(0, 0);
        int cnt = min(32, cnt_all - base);
        int k = 0;
        for (; k + 4 <= cnt; k += 4) {
            int   sa = __shfl_sync(FULL, ed.x, k);
            float wa = __int_as_float(__shfl_sync(FULL, ed.y, k));
            int   sb = __shfl_sync(FULL, ed.x, k + 1);
            float wb = __int_as_float(__shfl_sync(FULL, ed.y, k + 1));
            int   sc = __shfl_sync(FULL, ed.x, k + 2);
            float wc = __int_as_float(__shfl_sync(FULL, ed.y, k + 2));
            int   sd = __shfl_sync(FULL, ed.x, k + 3);
            float wd = __int_as_float(__shfl_sync(FULL, ed.y, k + 3));
            float2 va = *reinterpret_cast<const float2*>(&hsrc[(size_t)sa * DD + lane * 2]);
            float2 vb = *reinterpret_cast<const float2*>(&hsrc[(size_t)sb * DD + lane * 2]);
            float2 vc = *reinterpret_cast<const float2*>(&hsrc[(size_t)sc * DD + lane * 2]);
            float2 vd = *reinterpret_cast<const float2*>(&hsrc[(size_t)sd * DD + lane * 2]);
            ax += wa * va.x + wb * vb.x;
            ay += wa * va.y + wb * vb.y;
            ax += wc * vc.x + wd * vd.x;
            ay += wc * vc.y + wd * vd.y;
        }
        for (; k < cnt; k++) {
            int   sa = __shfl_sync(FULL, ed.x, k);
            float wa = __int_as_float(__shfl_sync(FULL, ed.y, k));
            float2 va = *reinterpret_cast<const float2*>(&hsrc[(size_t)sa * DD + lane * 2]);
            ax += wa * va.x; ay += wa * va.y;
        }
    }
    return make_float2(ax, ay);
}

// --------- warp matvec: y = xs @ W (row-major 64x64), float4 streaming ---------
__device__ __forceinline__ void warp_matvec_g(const float* __restrict__ Wn,
                                              const float* xs, int lane, float acc[4]) {
    acc[0] = acc[1] = acc[2] = acc[3] = 0.f;
    int half = lane >> 4;
    int coff = (lane & 15) * 4;
    #pragma unroll
    for (int d = 0; d < DD; d += 2) {
        float4 w4 = *reinterpret_cast<const float4*>(&Wn[(d + half) * DD + coff]);
        float xv = xs[d + half];
        acc[0] += xv * w4.x; acc[1] += xv * w4.y;
        acc[2] += xv * w4.z; acc[3] += xv * w4.w;
    }
    #pragma unroll
    for (int c = 0; c < 4; c++)
        acc[c] += __shfl_xor_sync(FULL, acc[c], 16);
}

// ---------------- conv1 lin: h1 = x @ Wc1 ----------------
__global__ __launch_bounds__(256) void gemm1_kernel(const float* __restrict__ x,
                                                    const float* __restrict__ Wc) {
    __shared__ float Ws[DD * DD];
    __shared__ float xs[8][DD];
    int tid = threadIdx.x;
    #pragma unroll
    for (int i = tid; i < DD * DD; i += 256) Ws[i] = Wc[i];
    int w = tid >> 5, lane = tid & 31;
    int node = blockIdx.x * 8 + w;
    *reinterpret_cast<float2*>(&xs[w][lane * 2]) =
        *reinterpret_cast<const float2*>(&x[(size_t)node * DD + lane * 2]);
    __syncthreads();
    float acc[4];
    warp_matvec_g(Ws, xs[w], lane, acc);
    if (lane < 16) {
        float4 o = make_float4(acc[0], acc[1], acc[2], acc[3]);
        *reinterpret_cast<float4*>(&g_h1[(size_t)node * DD + (lane & 15) * 4]) = o;
    }
}

// ---------------- conv2 fused: gather(h1) -> selu(+bc1) -> @Wc2 -> h2 ----------------
__global__ __launch_bounds__(256) void conv2_fused_kernel(const float* __restrict__ Wc,
                                                          const float* __restrict__ bin) {
    __shared__ float Ws[DD * DD];
    __shared__ float xs[8][DD];
    int tid = threadIdx.x;
    #pragma unroll
    for (int i = tid; i < DD * DD; i += 256) Ws[i] = Wc[i];
    int w = tid >> 5, lane = tid & 31;
    int node = blockIdx.x * 8 + w;
    float2 acc2 = gather_col2(g_h1, node, lane);
    xs[w][lane * 2]     = selu_f(acc2.x + bin[lane * 2]);
    xs[w][lane * 2 + 1] = selu_f(acc2.y + bin[lane * 2 + 1]);
    __syncthreads();
    float acc[4];
    warp_matvec_g(Ws, xs[w], lane, acc);
    if (lane < 16) {
        float4 o = make_float4(acc[0], acc[1], acc[2], acc[3]);
        *reinterpret_cast<float4*>(&g_h2[(size_t)node * DD + (lane & 15) * 4]) = o;
    }
}

// ------- final fused: gather(h2) -> selu(+bc2) -> W1 -> LN -> W2 -> out; restore state -------
__global__ __launch_bounds__(256) void final_fused_kernel(
        const float* __restrict__ bc2,
        const float* __restrict__ W1, const float* __restrict__ b1,
        const float* __restrict__ W2, const float* __restrict__ b2,
        const float* __restrict__ gam, const float* __restrict__ bet,
        float* __restrict__ out) {
    __shared__ float hs[8][DD];
    __shared__ float ts[8][DD];
    int tid = threadIdx.x;
    int w = tid >> 5, lane = tid & 31;
    int node = blockIdx.x * 8 + w;
    int coff = (lane & 15) * 4;

    float2 acc2 = gather_col2(g_h2, node, lane);
    // last use of g_cnt/g_deg this invocation: restore zeros for next graph replay
    if (lane == 0) { g_cnt[node] = 0; g_deg[node] = 0.f; }
    hs[w][lane * 2]     = selu_f(acc2.x + bc2[lane * 2]);
    hs[w][lane * 2 + 1] = selu_f(acc2.y + bc2[lane * 2 + 1]);
    __syncwarp();

    const float* W1n = W1 + (size_t)node * (DD * DD);
    float v[4];
    warp_matvec_g(W1n, hs[w], lane, v);
    float4 b1v = *reinterpret_cast<const float4*>(&b1[(size_t)node * DD + coff]);
    v[0] += b1v.x; v[1] += b1v.y; v[2] += b1v.z; v[3] += b1v.w;

    float s1 = v[0] + v[1] + v[2] + v[3];
    float s2 = v[0] * v[0] + v[1] * v[1] + v[2] * v[2] + v[3] * v[3];
    #pragma unroll
    for (int o = 8; o; o >>= 1) {
        s1 += __shfl_xor_sync(FULL, s1, o);
        s2 += __shfl_xor_sync(FULL, s2, o);
    }
    float mu  = s1 * (1.f / DD);
    float var = s2 * (1.f / DD) - mu * mu;
    float rstd = rsqrtf(var + 1e-5f);
    float4 gv = *reinterpret_cast<const float4*>(&gam[coff]);
    float4 bv = *reinterpret_cast<const float4*>(&bet[coff]);
    float t0 = (v[0] - mu) * rstd * gv.x + bv.x;
    float t1 = (v[1] - mu) * rstd * gv.y + bv.y;
    float t2 = (v[2] - mu) * rstd * gv.z + bv.z;
    float t3 = (v[3] - mu) * rstd * gv.w + bv.w;
    if (lane < 16)
        *reinterpret_cast<float4*>(&ts[w][coff]) = make_float4(t0, t1, t2, t3);
    __syncwarp();

    const float* W2n = W2 + (size_t)node * (DD * DD);
    float q[4];
    warp_matvec_g(W2n, ts[w], lane, q);
    if (lane < 16) {
        float4 b2v = *reinterpret_cast<const float4*>(&b2[(size_t)node * DD + coff]);
        float4 o = make_float4(q[0] + b2v.x, q[1] + b2v.y, q[2] + b2v.z, q[3] + b2v.w);
        *reinterpret_cast<float4*>(&out[(size_t)node * DD + coff]) = o;
    }
}

// ---------------- launch ----------------
extern "C" void kernel_launch(void* const* d_in, const int* in_sizes, int n_in,
                              void* d_out, int out_size) {
    const float* x   = (const float*)d_in[0];
    const int*   ei  = (const int*)d_in[1];
    const float* ew  = (const float*)d_in[2];
    const float* Wc1 = (const float*)d_in[3];
    const float* bc1 = (const float*)d_in[4];
    const float* Wc2 = (const float*)d_in[5];
    const float* bc2 = (const float*)d_in[6];
    const float* W1  = (const float*)d_in[7];
    const float* b1  = (const float*)d_in[8];
    const float* W2  = (const float*)d_in[9];
    const float* b2  = (const float*)d_in[10];
    const float* gam = (const float*)d_in[11];
    const float* bet = (const float*)d_in[12];
    float* out = (float*)d_out;

    static cudaStream_t s2 = 0;
    static cudaEvent_t evF = 0, evJ = 0;
    static int ready = 0;
    if (!ready) {
        bool ok = cudaStreamCreateWithFlags(&s2, cudaStreamNonBlocking) == cudaSuccess &&
                  cudaEventCreateWithFlags(&evF, cudaEventDisableTiming) == cudaSuccess &&
                  cudaEventCreateWithFlags(&evJ, cudaEventDisableTiming) == cudaSuccess;
        ready = ok ? 1 : -1;
    }

    bool fork = (ready == 1);
    if (fork) {
        cudaEventRecord(evF, 0);
        cudaStreamWaitEvent(s2, evF, 0);
        gemm1_kernel<<<NN / 8, 256, 0, s2>>>(x, Wc1);  // overlaps with prep chain
        cudaEventRecord(evJ, s2);
    }

    edge_prep_kernel<<<EE / 256, 256>>>(ei, ew);
    norm_fill_kernel<<<EE / 512, 256>>>(ew);

    if (fork)
        cudaStreamWaitEvent(0, evJ, 0);
    else
        gemm1_kernel<<<NN / 8, 256>>>(x, Wc1);

    conv2_fused_kernel<<<NN / 8, 256>>>(Wc2, bc1);
    final_fused_kernel<<<NN / 8, 256>>>(bc2, W1, b1, W2, b2, gam, bet, out);
}

// round 10
// speedup vs baseline: 1.3202x; 1.0527x over previous
#include <cuda_runtime.h>
#include <math.h>

#define NN 20000
#define EE 640000
#define DD 64
#define CAP 128          // ELL capacity per dst node (mean in-degree 32; P(>128) ~ 0)
#define FULL 0xffffffffu

// ---------------- scratch ----------------
// g_cnt / g_deg are zero at every kernel_launch entry: statically zero-initialized,
// and final_fused_kernel re-zeroes them after their last use within each invocation.
__device__ __align__(16) float g_deg[NN];
__device__ __align__(16) int   g_cnt[NN];
__device__ __align__(16) int   g_srcv[EE];
__device__ __align__(16) int   g_slot[EE];        // dst*CAP + rank
__device__ __align__(16) int2  g_ell[NN * CAP];   // (src, norm-bits)
__device__ __align__(16) float g_h1[NN * DD];
__device__ __align__(16) float g_h2[NN * DD];

__device__ __forceinline__ float selu_f(float x) {
    const float sc = 1.0507009873554805f;
    const float al = 1.6732632423543772f;
    return x > 0.f ? sc * x : sc * al * (expf(x) - 1.f);
}

// ---------------- edge extraction + degree + packed slot (dtype probe inlined) ----------------
__global__ __launch_bounds__(256) void edge_prep_kernel(const int* __restrict__ ei32,
                                                        const float* __restrict__ ew) {
    __shared__ int s_is64;
    int tid = threadIdx.x;
    if (tid < 32) {
        int ok = (ei32[2 * tid + 1] == 0) && (ei32[2 * (tid + 32) + 1] == 0);
        unsigned m = __ballot_sync(FULL, ok);
        if (tid == 0) s_is64 = (m == FULL);
    }
    __syncthreads();
    int is64 = s_is64;
    int e = blockIdx.x * 256 + tid;
    if (e >= EE) return;
    int s, d;
    if (is64) { s = ei32[2 * e]; d = ei32[2 * (EE + e)]; }
    else      { s = ei32[e];     d = ei32[EE + e]; }
    g_srcv[e] = s;
    atomicAdd(&g_deg[d], ew[e]);
    int rank = atomicAdd(&g_cnt[d], 1);
    g_slot[e] = d * CAP + rank;
}

// ---------------- norm + ELL placement (2 edges/thread) ----------------
__global__ __launch_bounds__(256) void norm_fill_kernel(const float* __restrict__ ew) {
    int e0 = blockIdx.x * blockDim.x + threadIdx.x;
    int e1 = e0 + EE / 2;
    if (e0 >= EE / 2) return;
    int s0 = g_srcv[e0], sl0 = g_slot[e0];
    int s1 = g_srcv[e1], sl1 = g_slot[e1];
    int d0 = sl0 >> 7, d1 = sl1 >> 7;
    float n0 = rsqrtf(1.f + g_deg[s0]) * ew[e0] * rsqrtf(1.f + g_deg[d0]);
    float n1 = rsqrtf(1.f + g_deg[s1]) * ew[e1] * rsqrtf(1.f + g_deg[d1]);
    g_ell[sl0] = make_int2(s0, __float_as_int(n0));
    g_ell[sl1] = make_int2(s1, __float_as_int(n1));
}

// ------- split-half ELL gather: each 16-lane half covers all 64 cols (float4/lane), -------
// ------- halves process different edges; xor-16 combine at the end.                -------
__device__ __forceinline__ float4 gather_col4(const float* __restrict__ hsrc,
                                              int n, int lane) {
    int cnt_all = g_cnt[n];
    const int2* row = &g_ell[(size_t)n * CAP];
    int half = lane >> 4;
    int coff = (lane & 15) * 4;
    float4 hv = *reinterpret_cast<const float4*>(&hsrc[(size_t)n * DD + coff]);
    float inv = (half == 0) ? 1.f / (1.f + g_deg[n]) : 0.f;  // self-loop once
    float a0 = hv.x * inv, a1 = hv.y * inv, a2 = hv.z * inv, a3 = hv.w * inv;
    for (int base = 0; base < cnt_all; base += 32) {
        int idx = base + lane;
        int2 ed = (idx < cnt_all) ? row[idx] : make_int2(0, 0);  // OOB: s=0, w=0 (no-op)
        int cnt = min(32, cnt_all - base);
        for (int k = 0; k < cnt; k += 4) {
            int sl0 = k + half;       // edges k, k+1 (one per half)
            int sl1 = k + 2 + half;   // edges k+2, k+3
            int   sA = __shfl_sync(FULL, ed.x, sl0);
            float wA = __int_as_float(__shfl_sync(FULL, ed.y, sl0));
            int   sB = __shfl_sync(FULL, ed.x, sl1);
            float wB = __int_as_float(__shfl_sync(FULL, ed.y, sl1));
            float4 vA = *reinterpret_cast<const float4*>(&hsrc[(size_t)sA * DD + coff]);
            float4 vB = *reinterpret_cast<const float4*>(&hsrc[(size_t)sB * DD + coff]);
            a0 += wA * vA.x + wB * vB.x;
            a1 += wA * vA.y + wB * vB.y;
            a2 += wA * vA.z + wB * vB.z;
            a3 += wA * vA.w + wB * vB.w;
        }
    }
    a0 += __shfl_xor_sync(FULL, a0, 16);
    a1 += __shfl_xor_sync(FULL, a1, 16);
    a2 += __shfl_xor_sync(FULL, a2, 16);
    a3 += __shfl_xor_sync(FULL, a3, 16);
    return make_float4(a0, a1, a2, a3);
}

// --------- warp matvec: y = xs @ W (row-major 64x64), float4 streaming ---------
__device__ __forceinline__ void warp_matvec_g(const float* __restrict__ Wn,
                                              const float* xs, int lane, float acc[4]) {
    acc[0] = acc[1] = acc[2] = acc[3] = 0.f;
    int half = lane >> 4;
    int coff = (lane & 15) * 4;
    #pragma unroll
    for (int d = 0; d < DD; d += 2) {
        float4 w4 = *reinterpret_cast<const float4*>(&Wn[(d + half) * DD + coff]);
        float xv = xs[d + half];
        acc[0] += xv * w4.x; acc[1] += xv * w4.y;
        acc[2] += xv * w4.z; acc[3] += xv * w4.w;
    }
    #pragma unroll
    for (int c = 0; c < 4; c++)
        acc[c] += __shfl_xor_sync(FULL, acc[c], 16);
}

// ---------------- conv1 lin: h1 = x @ Wc1 ----------------
__global__ __launch_bounds__(256) void gemm1_kernel(const float* __restrict__ x,
                                                    const float* __restrict__ Wc) {
    __shared__ float Ws[DD * DD];
    __shared__ float xs[8][DD];
    int tid = threadIdx.x;
    #pragma unroll
    for (int i = tid; i < DD * DD; i += 256) Ws[i] = Wc[i];
    int w = tid >> 5, lane = tid & 31;
    int node = blockIdx.x * 8 + w;
    *reinterpret_cast<float2*>(&xs[w][lane * 2]) =
        *reinterpret_cast<const float2*>(&x[(size_t)node * DD + lane * 2]);
    __syncthreads();
    float acc[4];
    warp_matvec_g(Ws, xs[w], lane, acc);
    if (lane < 16) {
        float4 o = make_float4(acc[0], acc[1], acc[2], acc[3]);
        *reinterpret_cast<float4*>(&g_h1[(size_t)node * DD + (lane & 15) * 4]) = o;
    }
}

// ---------------- conv2 fused: gather(h1) -> selu(+bc1) -> @Wc2 -> h2 ----------------
__global__ __launch_bounds__(256) void conv2_fused_kernel(const float* __restrict__ Wc,
                                                          const float* __restrict__ bin) {
    __shared__ float Ws[DD * DD];
    __shared__ float xs[8][DD];
    int tid = threadIdx.x;
    #pragma unroll
    for (int i = tid; i < DD * DD; i += 256) Ws[i] = Wc[i];
    int w = tid >> 5, lane = tid & 31;
    int node = blockIdx.x * 8 + w;
    int coff = (lane & 15) * 4;
    float4 a = gather_col4(g_h1, node, lane);
    if (lane < 16) {
        float4 bi = *reinterpret_cast<const float4*>(&bin[coff]);
        float4 sv = make_float4(selu_f(a.x + bi.x), selu_f(a.y + bi.y),
                                selu_f(a.z + bi.z), selu_f(a.w + bi.w));
        *reinterpret_cast<float4*>(&xs[w][coff]) = sv;
    }
    __syncthreads();
    float acc[4];
    warp_matvec_g(Ws, xs[w], lane, acc);
    if (lane < 16) {
        float4 o = make_float4(acc[0], acc[1], acc[2], acc[3]);
        *reinterpret_cast<float4*>(&g_h2[(size_t)node * DD + coff]) = o;
    }
}

// ------- final fused: gather(h2) -> selu(+bc2) -> W1 -> LN -> W2 -> out; restore state -------
__global__ __launch_bounds__(256) void final_fused_kernel(
        const float* __restrict__ bc2,
        const float* __restrict__ W1, const float* __restrict__ b1,
        const float* __restrict__ W2, const float* __restrict__ b2,
        const float* __restrict__ gam, const float* __restrict__ bet,
        float* __restrict__ out) {
    __shared__ float hs[8][DD];
    __shared__ float ts[8][DD];
    int tid = threadIdx.x;
    int w = tid >> 5, lane = tid & 31;
    int node = blockIdx.x * 8 + w;
    int coff = (lane & 15) * 4;

    float4 a = gather_col4(g_h2, node, lane);
    // last use of g_cnt/g_deg this invocation: restore zeros for next graph replay
    if (lane == 0) { g_cnt[node] = 0; g_deg[node] = 0.f; }
    if (lane < 16) {
        float4 bi = *reinterpret_cast<const float4*>(&bc2[coff]);
        float4 sv = make_float4(selu_f(a.x + bi.x), selu_f(a.y + bi.y),
                                selu_f(a.z + bi.z), selu_f(a.w + bi.w));
        *reinterpret_cast<float4*>(&hs[w][coff]) = sv;
    }
    __syncwarp();

    const float* W1n = W1 + (size_t)node * (DD * DD);
    float v[4];
    warp_matvec_g(W1n, hs[w], lane, v);
    float4 b1v = *reinterpret_cast<const float4*>(&b1[(size_t)node * DD + coff]);
    v[0] += b1v.x; v[1] += b1v.y; v[2] += b1v.z; v[3] += b1v.w;

    // layernorm: each 16-lane half holds all 64 values (4 per lane)
    float s1 = v[0] + v[1] + v[2] + v[3];
    float s2 = v[0] * v[0] + v[1] * v[1] + v[2] * v[2] + v[3] * v[3];
    #pragma unroll
    for (int o = 8; o; o >>= 1) {
        s1 += __shfl_xor_sync(FULL, s1, o);
        s2 += __shfl_xor_sync(FULL, s2, o);
    }
    float mu  = s1 * (1.f / DD);
    float var = s2 * (1.f / DD) - mu * mu;
    float rstd = rsqrtf(var + 1e-5f);
    float4 gv = *reinterpret_cast<const float4*>(&gam[coff]);
    float4 bv = *reinterpret_cast<const float4*>(&bet[coff]);
    float t0 = (v[0] - mu) * rstd * gv.x + bv.x;
    float t1 = (v[1] - mu) * rstd * gv.y + bv.y;
    float t2 = (v[2] - mu) * rstd * gv.z + bv.z;
    float t3 = (v[3] - mu) * rstd * gv.w + bv.w;
    if (lane < 16)
        *reinterpret_cast<float4*>(&ts[w][coff]) = make_float4(t0, t1, t2, t3);
    __syncwarp();

    const float* W2n = W2 + (size_t)node * (DD * DD);
    float q[4];
    warp_matvec_g(W2n, ts[w], lane, q);
    if (lane < 16) {
        float4 b2v = *reinterpret_cast<const float4*>(&b2[(size_t)node * DD + coff]);
        float4 o = make_float4(q[0] + b2v.x, q[1] + b2v.y, q[2] + b2v.z, q[3] + b2v.w);
        *reinterpret_cast<float4*>(&out[(size_t)node * DD + coff]) = o;
    }
}

// ---------------- launch ----------------
extern "C" void kernel_launch(void* const* d_in, const int* in_sizes, int n_in,
                              void* d_out, int out_size) {
    const float* x   = (const float*)d_in[0];
    const int*   ei  = (const int*)d_in[1];
    const float* ew  = (const float*)d_in[2];
    const float* Wc1 = (const float*)d_in[3];
    const float* bc1 = (const float*)d_in[4];
    const float* Wc2 = (const float*)d_in[5];
    const float* bc2 = (const float*)d_in[6];
    const float* W1  = (const float*)d_in[7];
    const float* b1  = (const float*)d_in[8];
    const float* W2  = (const float*)d_in[9];
    const float* b2  = (const float*)d_in[10];
    const float* gam = (const float*)d_in[11];
    const float* bet = (const float*)d_in[12];
    float* out = (float*)d_out;

    static cudaStream_t s2 = 0;
    static cudaEvent_t evF = 0, evJ = 0;
    static int ready = 0;
    if (!ready) {
        bool ok = cudaStreamCreateWithFlags(&s2, cudaStreamNonBlocking) == cudaSuccess &&
                  cudaEventCreateWithFlags(&evF, cudaEventDisableTiming) == cudaSuccess &&
                  cudaEventCreateWithFlags(&evJ, cudaEventDisableTiming) == cudaSuccess;
        ready = ok ? 1 : -1;
    }

    bool fork = (ready == 1);
    if (fork) {
        cudaEventRecord(evF, 0);
        cudaStreamWaitEvent(s2, evF, 0);
        gemm1_kernel<<<NN / 8, 256, 0, s2>>>(x, Wc1);  // overlaps with prep chain
        cudaEventRecord(evJ, s2);
    }

    edge_prep_kernel<<<EE / 256, 256>>>(ei, ew);
    norm_fill_kernel<<<EE / 512, 256>>>(ew);

    if (fork)
        cudaStreamWaitEvent(0, evJ, 0);
    else
        gemm1_kernel<<<NN / 8, 256>>>(x, Wc1);

    conv2_fused_kernel<<<NN / 8, 256>>>(Wc2, bc1);
    final_fused_kernel<<<NN / 8, 256>>>(bc2, W1, b1, W2, b2, gam, bet, out);
}

// round 11
// speedup vs baseline: 1.3427x; 1.0170x over previous
#include <cuda_runtime.h>
#include <math.h>

#define NN 20000
#define EE 640000
#define DD 64
#define CAP 128          // ELL capacity per dst node (mean in-degree 32; P(>128) ~ 0)
#define FULL 0xffffffffu

// ---------------- scratch ----------------
// g_cnt / g_deg are zero at every kernel_launch entry: statically zero-initialized,
// and final_fused_kernel re-zeroes them after their last (own-node) use each invocation.
__device__ __align__(16) float g_deg[NN];
__device__ __align__(16) int   g_cnt[NN];
__device__ __align__(16) int2  g_ell[NN * CAP];   // (src, weight-bits); conv2 folds dinv[src] in place
__device__ __align__(16) float g_h1[NN * DD];
__device__ __align__(16) float g_h2[NN * DD];

__device__ __forceinline__ float selu_f(float x) {
    const float sc = 1.0507009873554805f;
    const float al = 1.6732632423543772f;
    return x > 0.f ? sc * x : sc * al * (expf(x) - 1.f);
}

// ------- edge extraction + degree + direct ELL placement (single edge pass) -------
__global__ __launch_bounds__(256) void edge_prep_kernel(const int* __restrict__ ei32,
                                                        const float* __restrict__ ew) {
    __shared__ int s_is64;
    int tid = threadIdx.x;
    if (tid < 32) {
        int ok = (ei32[2 * tid + 1] == 0) && (ei32[2 * (tid + 32) + 1] == 0);
        unsigned m = __ballot_sync(FULL, ok);
        if (tid == 0) s_is64 = (m == FULL);
    }
    __syncthreads();
    int is64 = s_is64;
    int e = blockIdx.x * 256 + tid;
    if (e >= EE) return;
    int s, d;
    if (is64) { s = ei32[2 * e]; d = ei32[2 * (EE + e)]; }
    else      { s = ei32[e];     d = ei32[EE + e]; }
    float w = ew[e];
    atomicAdd(&g_deg[d], w);
    int rank = atomicAdd(&g_cnt[d], 1);
    g_ell[d * CAP + rank] = make_int2(s, __float_as_int(w));
}

// ------- split-half ELL gather, 8 edges/iter (4 per half), float4/lane. -------
// FOLD=true: ELL weight is raw ew; fold dinv[src] on the fly and write back.
// FOLD=false: ELL weight already folded.
// Returns dinv_n * sum + dinv_n^2 * h[n] (full GCN-normalized aggregate).
template <bool FOLD>
__device__ __forceinline__ float4 gather4(const float* __restrict__ hsrc,
                                          int n, int lane) {
    int cnt_all = g_cnt[n];
    int2* row = &g_ell[(size_t)n * CAP];
    int half = lane >> 4;
    int coff = (lane & 15) * 4;
    float dinv_n = rsqrtf(1.f + g_deg[n]);
    float4 hv = *reinterpret_cast<const float4*>(&hsrc[(size_t)n * DD + coff]);
    float a0 = 0.f, a1 = 0.f, a2 = 0.f, a3 = 0.f;
    for (int base = 0; base < cnt_all; base += 32) {
        int idx = base + lane;
        int sx = 0, wb = 0;
        if (idx < cnt_all) {
            int2 ed = row[idx];
            sx = ed.x;
            if (FOLD) {
                float wn = __int_as_float(ed.y) * rsqrtf(1.f + g_deg[sx]);
                wb = __float_as_int(wn);
                row[idx].y = wb;   // fold once; final gather reuses
            } else {
                wb = ed.y;
            }
        }
        int cnt = min(32, cnt_all - base);
        for (int k = 0; k < cnt; k += 8) {   // OOB shfl sources carry (0,0): harmless
            int i0 = k + half, i1 = k + 2 + half, i2 = k + 4 + half, i3 = k + 6 + half;
            int   s0 = __shfl_sync(FULL, sx, i0);
            float w0 = __int_as_float(__shfl_sync(FULL, wb, i0));
            int   s1 = __shfl_sync(FULL, sx, i1);
            float w1 = __int_as_float(__shfl_sync(FULL, wb, i1));
            int   s2 = __shfl_sync(FULL, sx, i2);
            float w2 = __int_as_float(__shfl_sync(FULL, wb, i2));
            int   s3 = __shfl_sync(FULL, sx, i3);
            float w3 = __int_as_float(__shfl_sync(FULL, wb, i3));
            float4 v0 = *reinterpret_cast<const float4*>(&hsrc[(size_t)s0 * DD + coff]);
            float4 v1 = *reinterpret_cast<const float4*>(&hsrc[(size_t)s1 * DD + coff]);
            float4 v2 = *reinterpret_cast<const float4*>(&hsrc[(size_t)s2 * DD + coff]);
            float4 v3 = *reinterpret_cast<const float4*>(&hsrc[(size_t)s3 * DD + coff]);
            a0 += w0 * v0.x + w1 * v1.x;  a0 += w2 * v2.x + w3 * v3.x;
            a1 += w0 * v0.y + w1 * v1.y;  a1 += w2 * v2.y + w3 * v3.y;
            a2 += w0 * v0.z + w1 * v1.z;  a2 += w2 * v2.z + w3 * v3.z;
            a3 += w0 * v0.w + w1 * v1.w;  a3 += w2 * v2.w + w3 * v3.w;
        }
    }
    a0 += __shfl_xor_sync(FULL, a0, 16);
    a1 += __shfl_xor_sync(FULL, a1, 16);
    a2 += __shfl_xor_sync(FULL, a2, 16);
    a3 += __shfl_xor_sync(FULL, a3, 16);
    float self = dinv_n * dinv_n;
    return make_float4(dinv_n * a0 + hv.x * self, dinv_n * a1 + hv.y * self,
                       dinv_n * a2 + hv.z * self, dinv_n * a3 + hv.w * self);
}

// --------- warp matvec: y = xs @ W (row-major 64x64), float4 streaming ---------
__device__ __forceinline__ void warp_matvec_g(const float* __restrict__ Wn,
                                              const float* xs, int lane, float acc[4]) {
    acc[0] = acc[1] = acc[2] = acc[3] = 0.f;
    int half = lane >> 4;
    int coff = (lane & 15) * 4;
    #pragma unroll
    for (int d = 0; d < DD; d += 2) {
        float4 w4 = *reinterpret_cast<const float4*>(&Wn[(d + half) * DD + coff]);
        float xv = xs[d + half];
        acc[0] += xv * w4.x; acc[1] += xv * w4.y;
        acc[2] += xv * w4.z; acc[3] += xv * w4.w;
    }
    #pragma unroll
    for (int c = 0; c < 4; c++)
        acc[c] += __shfl_xor_sync(FULL, acc[c], 16);
}

// ---------------- conv1 lin: h1 = x @ Wc1 ----------------
__global__ __launch_bounds__(256) void gemm1_kernel(const float* __restrict__ x,
                                                    const float* __restrict__ Wc) {
    __shared__ float Ws[DD * DD];
    __shared__ float xs[8][DD];
    int tid = threadIdx.x;
    #pragma unroll
    for (int i = tid; i < DD * DD; i += 256) Ws[i] = Wc[i];
    int w = tid >> 5, lane = tid & 31;
    int node = blockIdx.x * 8 + w;
    *reinterpret_cast<float2*>(&xs[w][lane * 2]) =
        *reinterpret_cast<const float2*>(&x[(size_t)node * DD + lane * 2]);
    __syncthreads();
    float acc[4];
    warp_matvec_g(Ws, xs[w], lane, acc);
    if (lane < 16) {
        float4 o = make_float4(acc[0], acc[1], acc[2], acc[3]);
        *reinterpret_cast<float4*>(&g_h1[(size_t)node * DD + (lane & 15) * 4]) = o;
    }
}

// ---------------- conv2 fused: gather(h1, fold dinv_s) -> selu(+bc1) -> @Wc2 -> h2 ----------------
__global__ __launch_bounds__(256) void conv2_fused_kernel(const float* __restrict__ Wc,
                                                          const float* __restrict__ bin) {
    __shared__ float Ws[DD * DD];
    __shared__ float xs[8][DD];
    int tid = threadIdx.x;
    #pragma unroll
    for (int i = tid; i < DD * DD; i += 256) Ws[i] = Wc[i];
    int w = tid >> 5, lane = tid & 31;
    int node = blockIdx.x * 8 + w;
    int coff = (lane & 15) * 4;
    float4 a = gather4<true>(g_h1, node, lane);
    if (lane < 16) {
        float4 bi = *reinterpret_cast<const float4*>(&bin[coff]);
        float4 sv = make_float4(selu_f(a.x + bi.x), selu_f(a.y + bi.y),
                                selu_f(a.z + bi.z), selu_f(a.w + bi.w));
        *reinterpret_cast<float4*>(&xs[w][coff]) = sv;
    }
    __syncthreads();
    float acc[4];
    warp_matvec_g(Ws, xs[w], lane, acc);
    if (lane < 16) {
        float4 o = make_float4(acc[0], acc[1], acc[2], acc[3]);
        *reinterpret_cast<float4*>(&g_h2[(size_t)node * DD + coff]) = o;
    }
}

// ------- final fused: gather(h2) -> selu(+bc2) -> W1 -> LN -> W2 -> out; restore state -------
__global__ __launch_bounds__(256) void final_fused_kernel(
        const float* __restrict__ bc2,
        const float* __restrict__ W1, const float* __restrict__ b1,
        const float* __restrict__ W2, const float* __restrict__ b2,
        const float* __restrict__ gam, const float* __restrict__ bet,
        float* __restrict__ out) {
    __shared__ float hs[8][DD];
    __shared__ float ts[8][DD];
    int tid = threadIdx.x;
    int w = tid >> 5, lane = tid & 31;
    int node = blockIdx.x * 8 + w;
    int coff = (lane & 15) * 4;

    float4 a = gather4<false>(g_h2, node, lane);
    // last use of g_cnt/g_deg (own node only in this kernel): restore zeros for next replay
    if (lane == 0) { g_cnt[node] = 0; g_deg[node] = 0.f; }
    if (lane < 16) {
        float4 bi = *reinterpret_cast<const float4*>(&bc2[coff]);
        float4 sv = make_float4(selu_f(a.x + bi.x), selu_f(a.y + bi.y),
                                selu_f(a.z + bi.z), selu_f(a.w + bi.w));
        *reinterpret_cast<float4*>(&hs[w][coff]) = sv;
    }
    __syncwarp();

    const float* W1n = W1 + (size_t)node * (DD * DD);
    float v[4];
    warp_matvec_g(W1n, hs[w], lane, v);
    float4 b1v = *reinterpret_cast<const float4*>(&b1[(size_t)node * DD + coff]);
    v[0] += b1v.x; v[1] += b1v.y; v[2] += b1v.z; v[3] += b1v.w;

    // layernorm: each 16-lane half holds all 64 values (4 per lane)
    float s1 = v[0] + v[1] + v[2] + v[3];
    float s2 = v[0] * v[0] + v[1] * v[1] + v[2] * v[2] + v[3] * v[3];
    #pragma unroll
    for (int o = 8; o; o >>= 1) {
        s1 += __shfl_xor_sync(FULL, s1, o);
        s2 += __shfl_xor_sync(FULL, s2, o);
    }
    float mu  = s1 * (1.f / DD);
    float var = s2 * (1.f / DD) - mu * mu;
    float rstd = rsqrtf(var + 1e-5f);
    float4 gv = *reinterpret_cast<const float4*>(&gam[coff]);
    float4 bv = *reinterpret_cast<const float4*>(&bet[coff]);
    float t0 = (v[0] - mu) * rstd * gv.x + bv.x;
    float t1 = (v[1] - mu) * rstd * gv.y + bv.y;
    float t2 = (v[2] - mu) * rstd * gv.z + bv.z;
    float t3 = (v[3] - mu) * rstd * gv.w + bv.w;
    if (lane < 16)
        *reinterpret_cast<float4*>(&ts[w][coff]) = make_float4(t0, t1, t2, t3);
    __syncwarp();

    const float* W2n = W2 + (size_t)node * (DD * DD);
    float q[4];
    warp_matvec_g(W2n, ts[w], lane, q);
    if (lane < 16) {
        float4 b2v = *reinterpret_cast<const float4*>(&b2[(size_t)node * DD + coff]);
        float4 o = make_float4(q[0] + b2v.x, q[1] + b2v.y, q[2] + b2v.z, q[3] + b2v.w);
        *reinterpret_cast<float4*>(&out[(size_t)node * DD + coff]) = o;
    }
}

// ---------------- launch ----------------
extern "C" void kernel_launch(void* const* d_in, const int* in_sizes, int n_in,
                              void* d_out, int out_size) {
    const float* x   = (const float*)d_in[0];
    const int*   ei  = (const int*)d_in[1];
    const float* ew  = (const float*)d_in[2];
    const float* Wc1 = (const float*)d_in[3];
    const float* bc1 = (const float*)d_in[4];
    const float* Wc2 = (const float*)d_in[5];
    const float* bc2 = (const float*)d_in[6];
    const float* W1  = (const float*)d_in[7];
    const float* b1  = (const float*)d_in[8];
    const float* W2  = (const float*)d_in[9];
    const float* b2  = (const float*)d_in[10];
    const float* gam = (const float*)d_in[11];
    const float* bet = (const float*)d_in[12];
    float* out = (float*)d_out;

    static cudaStream_t s2 = 0;
    static cudaEvent_t evF = 0, evJ = 0;
    static int ready = 0;
    if (!ready) {
        bool ok = cudaStreamCreateWithFlags(&s2, cudaStreamNonBlocking) == cudaSuccess &&
                  cudaEventCreateWithFlags(&evF, cudaEventDisableTiming) == cudaSuccess &&
                  cudaEventCreateWithFlags(&evJ, cudaEventDisableTiming) == cudaSuccess;
        ready = ok ? 1 : -1;
    }

    bool fork = (ready == 1);
    if (fork) {
        cudaEventRecord(evF, 0);
        cudaStreamWaitEvent(s2, evF, 0);
        gemm1_kernel<<<NN / 8, 256, 0, s2>>>(x, Wc1);  // overlaps with edge_prep
        cudaEventRecord(evJ, s2);
    }

    edge_prep_kernel<<<EE / 256, 256>>>(ei, ew);

    if (fork)
        cudaStreamWaitEvent(0, evJ, 0);
    else
        gemm1_kernel<<<NN / 8, 256>>>(x, Wc1);

    conv2_fused_kernel<<<NN / 8, 256>>>(Wc2, bc1);
    final_fused_kernel<<<NN / 8, 256>>>(bc2, W1, b1, W2, b2, gam, bet, out);
}

// round 12
// speedup vs baseline: 1.4794x; 1.1018x over previous
#include <cuda_runtime.h>
#include <math.h>

#define NN 20000
#define EE 640000
#define DD 64
#define CAP 128          // ELL capacity per dst node (mean in-degree 32; P(>128) ~ 0)
#define FULL 0xffffffffu

// ---------------- scratch ----------------
// g_cnt / g_deg are zero at every kernel_launch entry: statically zero-initialized,
// and final_fused_kernel re-zeroes them after their last (own-node) use each invocation.
__device__ __align__(16) float g_deg[NN];
__device__ __align__(16) int   g_cnt[NN];
__device__ __align__(16) int2  g_ell[NN * CAP];   // (src, weight-bits); conv2 folds dinv[src] in place
__device__ __align__(16) float g_h1[NN * DD];
__device__ __align__(16) float g_h2[NN * DD];

__device__ __forceinline__ float selu_f(float x) {
    const float sc = 1.0507009873554805f;
    const float al = 1.6732632423543772f;
    return x > 0.f ? sc * x : sc * al * (expf(x) - 1.f);
}

// ------- edge extraction + degree + direct ELL placement (single edge pass) -------
__global__ __launch_bounds__(256) void edge_prep_kernel(const int* __restrict__ ei32,
                                                        const float* __restrict__ ew) {
    __shared__ int s_is64;
    int tid = threadIdx.x;
    if (tid < 32) {
        int ok = (ei32[2 * tid + 1] == 0) && (ei32[2 * (tid + 32) + 1] == 0);
        unsigned m = __ballot_sync(FULL, ok);
        if (tid == 0) s_is64 = (m == FULL);
    }
    __syncthreads();
    int is64 = s_is64;
    int e = blockIdx.x * 256 + tid;
    if (e >= EE) return;
    int s, d;
    if (is64) { s = __ldcs(&ei32[2 * e]); d = __ldcs(&ei32[2 * (EE + e)]); }
    else      { s = __ldcs(&ei32[e]);     d = __ldcs(&ei32[EE + e]); }
    float w = __ldcs(&ew[e]);
    atomicAdd(&g_deg[d], w);
    int rank = atomicAdd(&g_cnt[d], 1);
    g_ell[d * CAP + rank] = make_int2(s, __float_as_int(w));
}

// ------- split-half ELL gather, 16 edges/iter (8 per half), float4/lane. -------
// FOLD=true: ELL weight is raw ew; fold dinv[src] on the fly and write back.
// FOLD=false: ELL weight already folded.
// Returns dinv_n * sum + dinv_n^2 * h[n].
template <bool FOLD>
__device__ __forceinline__ float4 gather4(const float* __restrict__ hsrc,
                                          int n, int lane) {
    int cnt_all = g_cnt[n];
    int2* row = &g_ell[(size_t)n * CAP];
    int half = lane >> 4;
    int coff = (lane & 15) * 4;
    float dinv_n = rsqrtf(1.f + g_deg[n]);
    float4 hv = *reinterpret_cast<const float4*>(&hsrc[(size_t)n * DD + coff]);
    float a0 = 0.f, a1 = 0.f, a2 = 0.f, a3 = 0.f;
    for (int base = 0; base < cnt_all; base += 32) {
        int idx = base + lane;
        int sx = 0, wb = 0;
        if (idx < cnt_all) {
            int2 ed = row[idx];
            sx = ed.x;
            if (FOLD) {
                float wn = __int_as_float(ed.y) * rsqrtf(1.f + g_deg[sx]);
                wb = __float_as_int(wn);
                row[idx].y = wb;   // fold once; final gather reuses
            } else {
                wb = ed.y;
            }
        }
        int cnt = min(32, cnt_all - base);
        for (int k = 0; k < cnt; k += 16) {  // OOB shfl sources carry (0,0): harmless
            int   s0 = __shfl_sync(FULL, sx, k + half);
            float w0 = __int_as_float(__shfl_sync(FULL, wb, k + half));
            int   s1 = __shfl_sync(FULL, sx, k + 2 + half);
            float w1 = __int_as_float(__shfl_sync(FULL, wb, k + 2 + half));
            int   s2 = __shfl_sync(FULL, sx, k + 4 + half);
            float w2 = __int_as_float(__shfl_sync(FULL, wb, k + 4 + half));
            int   s3 = __shfl_sync(FULL, sx, k + 6 + half);
            float w3 = __int_as_float(__shfl_sync(FULL, wb, k + 6 + half));
            int   s4 = __shfl_sync(FULL, sx, k + 8 + half);
            float w4 = __int_as_float(__shfl_sync(FULL, wb, k + 8 + half));
            int   s5 = __shfl_sync(FULL, sx, k + 10 + half);
            float w5 = __int_as_float(__shfl_sync(FULL, wb, k + 10 + half));
            int   s6 = __shfl_sync(FULL, sx, k + 12 + half);
            float w6 = __int_as_float(__shfl_sync(FULL, wb, k + 12 + half));
            int   s7 = __shfl_sync(FULL, sx, k + 14 + half);
            float w7 = __int_as_float(__shfl_sync(FULL, wb, k + 14 + half));
            float4 v0 = *reinterpret_cast<const float4*>(&hsrc[(size_t)s0 * DD + coff]);
            float4 v1 = *reinterpret_cast<const float4*>(&hsrc[(size_t)s1 * DD + coff]);
            float4 v2 = *reinterpret_cast<const float4*>(&hsrc[(size_t)s2 * DD + coff]);
            float4 v3 = *reinterpret_cast<const float4*>(&hsrc[(size_t)s3 * DD + coff]);
            float4 v4 = *reinterpret_cast<const float4*>(&hsrc[(size_t)s4 * DD + coff]);
            float4 v5 = *reinterpret_cast<const float4*>(&hsrc[(size_t)s5 * DD + coff]);
            float4 v6 = *reinterpret_cast<const float4*>(&hsrc[(size_t)s6 * DD + coff]);
            float4 v7 = *reinterpret_cast<const float4*>(&hsrc[(size_t)s7 * DD + coff]);
            a0 += w0 * v0.x + w1 * v1.x;  a1 += w0 * v0.y + w1 * v1.y;
            a2 += w0 * v0.z + w1 * v1.z;  a3 += w0 * v0.w + w1 * v1.w;
            a0 += w2 * v2.x + w3 * v3.x;  a1 += w2 * v2.y + w3 * v3.y;
            a2 += w2 * v2.z + w3 * v3.z;  a3 += w2 * v2.w + w3 * v3.w;
            a0 += w4 * v4.x + w5 * v5.x;  a1 += w4 * v4.y + w5 * v5.y;
            a2 += w4 * v4.z + w5 * v5.z;  a3 += w4 * v4.w + w5 * v5.w;
            a0 += w6 * v6.x + w7 * v7.x;  a1 += w6 * v6.y + w7 * v7.y;
            a2 += w6 * v6.z + w7 * v7.z;  a3 += w6 * v6.w + w7 * v7.w;
        }
    }
    a0 += __shfl_xor_sync(FULL, a0, 16);
    a1 += __shfl_xor_sync(FULL, a1, 16);
    a2 += __shfl_xor_sync(FULL, a2, 16);
    a3 += __shfl_xor_sync(FULL, a3, 16);
    float self = dinv_n * dinv_n;
    return make_float4(dinv_n * a0 + hv.x * self, dinv_n * a1 + hv.y * self,
                       dinv_n * a2 + hv.z * self, dinv_n * a3 + hv.w * self);
}

// --------- warp matvec from SMEM weights ---------
__device__ __forceinline__ void warp_matvec_s(const float* Wn,
                                              const float* xs, int lane, float acc[4]) {
    acc[0] = acc[1] = acc[2] = acc[3] = 0.f;
    int half = lane >> 4;
    int coff = (lane & 15) * 4;
    #pragma unroll
    for (int d = 0; d < DD; d += 2) {
        float4 w4 = *reinterpret_cast<const float4*>(&Wn[(d + half) * DD + coff]);
        float xv = xs[d + half];
        acc[0] += xv * w4.x; acc[1] += xv * w4.y;
        acc[2] += xv * w4.z; acc[3] += xv * w4.w;
    }
    #pragma unroll
    for (int c = 0; c < 4; c++)
        acc[c] += __shfl_xor_sync(FULL, acc[c], 16);
}

// --------- warp matvec from GLOBAL weights, streaming (evict-first) ---------
__device__ __forceinline__ void warp_matvec_cs(const float* __restrict__ Wn,
                                               const float* xs, int lane, float acc[4]) {
    acc[0] = acc[1] = acc[2] = acc[3] = 0.f;
    int half = lane >> 4;
    int coff = (lane & 15) * 4;
    #pragma unroll
    for (int d = 0; d < DD; d += 2) {
        float4 w4 = __ldcs(reinterpret_cast<const float4*>(&Wn[(d + half) * DD + coff]));
        float xv = xs[d + half];
        acc[0] += xv * w4.x; acc[1] += xv * w4.y;
        acc[2] += xv * w4.z; acc[3] += xv * w4.w;
    }
    #pragma unroll
    for (int c = 0; c < 4; c++)
        acc[c] += __shfl_xor_sync(FULL, acc[c], 16);
}

// ---------------- conv1 lin: h1 = x @ Wc1 ----------------
__global__ __launch_bounds__(256) void gemm1_kernel(const float* __restrict__ x,
                                                    const float* __restrict__ Wc) {
    __shared__ float Ws[DD * DD];
    __shared__ float xs[8][DD];
    int tid = threadIdx.x;
    #pragma unroll
    for (int i = tid; i < DD * DD; i += 256) Ws[i] = Wc[i];
    int w = tid >> 5, lane = tid & 31;
    int node = blockIdx.x * 8 + w;
    *reinterpret_cast<float2*>(&xs[w][lane * 2]) =
        *reinterpret_cast<const float2*>(&x[(size_t)node * DD + lane * 2]);
    __syncthreads();
    float acc[4];
    warp_matvec_s(Ws, xs[w], lane, acc);
    if (lane < 16) {
        float4 o = make_float4(acc[0], acc[1], acc[2], acc[3]);
        *reinterpret_cast<float4*>(&g_h1[(size_t)node * DD + (lane & 15) * 4]) = o;
    }
}

// ---------------- conv2 fused: gather(h1, fold dinv_s) -> selu(+bc1) -> @Wc2 -> h2 ----------------
__global__ __launch_bounds__(256, 4) void conv2_fused_kernel(const float* __restrict__ Wc,
                                                             const float* __restrict__ bin) {
    __shared__ float Ws[DD * DD];
    __shared__ float xs[8][DD];
    int tid = threadIdx.x;
    #pragma unroll
    for (int i = tid; i < DD * DD; i += 256) Ws[i] = Wc[i];
    int w = tid >> 5, lane = tid & 31;
    int node = blockIdx.x * 8 + w;
    int coff = (lane & 15) * 4;
    float4 a = gather4<true>(g_h1, node, lane);
    if (lane < 16) {
        float4 bi = *reinterpret_cast<const float4*>(&bin[coff]);
        float4 sv = make_float4(selu_f(a.x + bi.x), selu_f(a.y + bi.y),
                                selu_f(a.z + bi.z), selu_f(a.w + bi.w));
        *reinterpret_cast<float4*>(&xs[w][coff]) = sv;
    }
    __syncthreads();
    float acc[4];
    warp_matvec_s(Ws, xs[w], lane, acc);
    if (lane < 16) {
        float4 o = make_float4(acc[0], acc[1], acc[2], acc[3]);
        *reinterpret_cast<float4*>(&g_h2[(size_t)node * DD + coff]) = o;
    }
}

// ------- final fused: gather(h2) -> selu(+bc2) -> W1 -> LN -> W2 -> out; restore state -------
__global__ __launch_bounds__(256, 4) void final_fused_kernel(
        const float* __restrict__ bc2,
        const float* __restrict__ W1, const float* __restrict__ b1,
        const float* __restrict__ W2, const float* __restrict__ b2,
        const float* __restrict__ gam, const float* __restrict__ bet,
        float* __restrict__ out) {
    __shared__ float hs[8][DD];
    __shared__ float ts[8][DD];
    int tid = threadIdx.x;
    int w = tid >> 5, lane = tid & 31;
    int node = blockIdx.x * 8 + w;
    int coff = (lane & 15) * 4;

    float4 a = gather4<false>(g_h2, node, lane);
    // last use of g_cnt/g_deg (own node only in this kernel): restore zeros for next replay
    if (lane == 0) { g_cnt[node] = 0; g_deg[node] = 0.f; }
    if (lane < 16) {
        float4 bi = *reinterpret_cast<const float4*>(&bc2[coff]);
        float4 sv = make_float4(selu_f(a.x + bi.x), selu_f(a.y + bi.y),
                                selu_f(a.z + bi.z), selu_f(a.w + bi.w));
        *reinterpret_cast<float4*>(&hs[w][coff]) = sv;
    }
    __syncwarp();

    const float* W1n = W1 + (size_t)node * (DD * DD);
    float v[4];
    warp_matvec_cs(W1n, hs[w], lane, v);
    float4 b1v = __ldcs(reinterpret_cast<const float4*>(&b1[(size_t)node * DD + coff]));
    v[0] += b1v.x; v[1] += b1v.y; v[2] += b1v.z; v[3] += b1v.w;

    // layernorm: each 16-lane half holds all 64 values (4 per lane)
    float s1 = v[0] + v[1] + v[2] + v[3];
    float s2 = v[0] * v[0] + v[1] * v[1] + v[2] * v[2] + v[3] * v[3];
    #pragma unroll
    for (int o = 8; o; o >>= 1) {
        s1 += __shfl_xor_sync(FULL, s1, o);
        s2 += __shfl_xor_sync(FULL, s2, o);
    }
    float mu  = s1 * (1.f / DD);
    float var = s2 * (1.f / DD) - mu * mu;
    float rstd = rsqrtf(var + 1e-5f);
    float4 gv = *reinterpret_cast<const float4*>(&gam[coff]);
    float4 bv = *reinterpret_cast<const float4*>(&bet[coff]);
    float t0 = (v[0] - mu) * rstd * gv.x + bv.x;
    float t1 = (v[1] - mu) * rstd * gv.y + bv.y;
    float t2 = (v[2] - mu) * rstd * gv.z + bv.z;
    float t3 = (v[3] - mu) * rstd * gv.w + bv.w;
    if (lane < 16)
        *reinterpret_cast<float4*>(&ts[w][coff]) = make_float4(t0, t1, t2, t3);
    __syncwarp();

    const float* W2n = W2 + (size_t)node * (DD * DD);
    float q[4];
    warp_matvec_cs(W2n, ts[w], lane, q);
    if (lane < 16) {
        float4 b2v = __ldcs(reinterpret_cast<const float4*>(&b2[(size_t)node * DD + coff]));
        float4 o = make_float4(q[0] + b2v.x, q[1] + b2v.y, q[2] + b2v.z, q[3] + b2v.w);
        *reinterpret_cast<float4*>(&out[(size_t)node * DD + coff]) = o;
    }
}

// ---------------- launch ----------------
extern "C" void kernel_launch(void* const* d_in, const int* in_sizes, int n_in,
                              void* d_out, int out_size) {
    const float* x   = (const float*)d_in[0];
    const int*   ei  = (const int*)d_in[1];
    const float* ew  = (const float*)d_in[2];
    const float* Wc1 = (const float*)d_in[3];
    const float* bc1 = (const float*)d_in[4];
    const float* Wc2 = (const float*)d_in[5];
    const float* bc2 = (const float*)d_in[6];
    const float* W1  = (const float*)d_in[7];
    const float* b1  = (const float*)d_in[8];
    const float* W2  = (const float*)d_in[9];
    const float* b2  = (const float*)d_in[10];
    const float* gam = (const float*)d_in[11];
    const float* bet = (const float*)d_in[12];
    float* out = (float*)d_out;

    static cudaStream_t s2 = 0;
    static cudaEvent_t evF = 0, evJ = 0;
    static int ready = 0;
    if (!ready) {
        bool ok = cudaStreamCreateWithFlags(&s2, cudaStreamNonBlocking) == cudaSuccess &&
                  cudaEventCreateWithFlags(&evF, cudaEventDisableTiming) == cudaSuccess &&
                  cudaEventCreateWithFlags(&evJ, cudaEventDisableTiming) == cudaSuccess;
        ready = ok ? 1 : -1;
    }

    bool fork = (ready == 1);
    if (fork) {
        cudaEventRecord(evF, 0);
        cudaStreamWaitEvent(s2, evF, 0);
        gemm1_kernel<<<NN / 8, 256, 0, s2>>>(x, Wc1);  // overlaps with edge_prep
        cudaEventRecord(evJ, s2);
    }

    edge_prep_kernel<<<EE / 256, 256>>>(ei, ew);

    if (fork)
        cudaStreamWaitEvent(0, evJ, 0);
    else
        gemm1_kernel<<<NN / 8, 256>>>(x, Wc1);

    conv2_fused_kernel<<<NN / 8, 256>>>(Wc2, bc1);
    final_fused_kernel<<<NN / 8, 256>>>(bc2, W1, b1, W2, b2, gam, bet, out);
}

// round 13
// speedup vs baseline: 1.5735x; 1.0636x over previous
#include <cuda_runtime.h>
#include <math.h>

#define NN 20000
#define EE 640000
#define DD 64
#define CAP 128          // ELL capacity per dst node (mean in-degree 32; P(>128) ~ 0)
#define FULL 0xffffffffu

// ---------------- scratch ----------------
// g_cnt / g_deg are zero at every kernel_launch entry: statically zero-initialized,
// and final_fused_kernel re-zeroes them after their last (own-node) use each invocation.
__device__ __align__(16) float g_deg[NN];
__device__ __align__(16) int   g_cnt[NN];
__device__ __align__(16) int2  g_ell[NN * CAP];   // (src, weight-bits); conv2 folds dinv[src] in place
__device__ __align__(16) float g_h1[NN * DD];
__device__ __align__(16) float g_h2[NN * DD];

__device__ __forceinline__ float selu_f(float x) {
    const float sc = 1.0507009873554805f;
    const float al = 1.6732632423543772f;
    return x > 0.f ? sc * x : sc * al * (expf(x) - 1.f);
}

// ------- split-half ELL gather, 16 edges/iter (8 per half), float4/lane. -------
// FOLD=true: ELL weight is raw ew; fold dinv[src] on the fly and write back.
// FOLD=false: ELL weight already folded.
// Returns dinv_n * sum + dinv_n^2 * h[n].
template <bool FOLD>
__device__ __forceinline__ float4 gather4(const float* __restrict__ hsrc,
                                          int n, int lane) {
    int cnt_all = g_cnt[n];
    int2* row = &g_ell[(size_t)n * CAP];
    int half = lane >> 4;
    int coff = (lane & 15) * 4;
    float dinv_n = rsqrtf(1.f + g_deg[n]);
    float4 hv = *reinterpret_cast<const float4*>(&hsrc[(size_t)n * DD + coff]);
    float a0 = 0.f, a1 = 0.f, a2 = 0.f, a3 = 0.f;
    for (int base = 0; base < cnt_all; base += 32) {
        int idx = base + lane;
        int sx = 0, wb = 0;
        if (idx < cnt_all) {
            int2 ed = row[idx];
            sx = ed.x;
            if (FOLD) {
                float wn = __int_as_float(ed.y) * rsqrtf(1.f + g_deg[sx]);
                wb = __float_as_int(wn);
                row[idx].y = wb;   // fold once; final gather reuses
            } else {
                wb = ed.y;
            }
        }
        int cnt = min(32, cnt_all - base);
        for (int k = 0; k < cnt; k += 16) {  // OOB shfl sources carry (0,0): harmless
            int   s0 = __shfl_sync(FULL, sx, k + half);
            float w0 = __int_as_float(__shfl_sync(FULL, wb, k + half));
            int   s1 = __shfl_sync(FULL, sx, k + 2 + half);
            float w1 = __int_as_float(__shfl_sync(FULL, wb, k + 2 + half));
            int   s2 = __shfl_sync(FULL, sx, k + 4 + half);
            float w2 = __int_as_float(__shfl_sync(FULL, wb, k + 4 + half));
            int   s3 = __shfl_sync(FULL, sx, k + 6 + half);
            float w3 = __int_as_float(__shfl_sync(FULL, wb, k + 6 + half));
            int   s4 = __shfl_sync(FULL, sx, k + 8 + half);
            float w4 = __int_as_float(__shfl_sync(FULL, wb, k + 8 + half));
            int   s5 = __shfl_sync(FULL, sx, k + 10 + half);
            float w5 = __int_as_float(__shfl_sync(FULL, wb, k + 10 + half));
            int   s6 = __shfl_sync(FULL, sx, k + 12 + half);
            float w6 = __int_as_float(__shfl_sync(FULL, wb, k + 12 + half));
            int   s7 = __shfl_sync(FULL, sx, k + 14 + half);
            float w7 = __int_as_float(__shfl_sync(FULL, wb, k + 14 + half));
            float4 v0 = *reinterpret_cast<const float4*>(&hsrc[(size_t)s0 * DD + coff]);
            float4 v1 = *reinterpret_cast<const float4*>(&hsrc[(size_t)s1 * DD + coff]);
            float4 v2 = *reinterpret_cast<const float4*>(&hsrc[(size_t)s2 * DD + coff]);
            float4 v3 = *reinterpret_cast<const float4*>(&hsrc[(size_t)s3 * DD + coff]);
            float4 v4 = *reinterpret_cast<const float4*>(&hsrc[(size_t)s4 * DD + coff]);
            float4 v5 = *reinterpret_cast<const float4*>(&hsrc[(size_t)s5 * DD + coff]);
            float4 v6 = *reinterpret_cast<const float4*>(&hsrc[(size_t)s6 * DD + coff]);
            float4 v7 = *reinterpret_cast<const float4*>(&hsrc[(size_t)s7 * DD + coff]);
            a0 += w0 * v0.x + w1 * v1.x;  a1 += w0 * v0.y + w1 * v1.y;
            a2 += w0 * v0.z + w1 * v1.z;  a3 += w0 * v0.w + w1 * v1.w;
            a0 += w2 * v2.x + w3 * v3.x;  a1 += w2 * v2.y + w3 * v3.y;
            a2 += w2 * v2.z + w3 * v3.z;  a3 += w2 * v2.w + w3 * v3.w;
            a0 += w4 * v4.x + w5 * v5.x;  a1 += w4 * v4.y + w5 * v5.y;
            a2 += w4 * v4.z + w5 * v5.z;  a3 += w4 * v4.w + w5 * v5.w;
            a0 += w6 * v6.x + w7 * v7.x;  a1 += w6 * v6.y + w7 * v7.y;
            a2 += w6 * v6.z + w7 * v7.z;  a3 += w6 * v6.w + w7 * v7.w;
        }
    }
    a0 += __shfl_xor_sync(FULL, a0, 16);
    a1 += __shfl_xor_sync(FULL, a1, 16);
    a2 += __shfl_xor_sync(FULL, a2, 16);
    a3 += __shfl_xor_sync(FULL, a3, 16);
    float self = dinv_n * dinv_n;
    return make_float4(dinv_n * a0 + hv.x * self, dinv_n * a1 + hv.y * self,
                       dinv_n * a2 + hv.z * self, dinv_n * a3 + hv.w * self);
}

// --------- warp matvec from SMEM weights ---------
__device__ __forceinline__ void warp_matvec_s(const float* Wn,
                                              const float* xs, int lane, float acc[4]) {
    acc[0] = acc[1] = acc[2] = acc[3] = 0.f;
    int half = lane >> 4;
    int coff = (lane & 15) * 4;
    #pragma unroll
    for (int d = 0; d < DD; d += 2) {
        float4 w4 = *reinterpret_cast<const float4*>(&Wn[(d + half) * DD + coff]);
        float xv = xs[d + half];
        acc[0] += xv * w4.x; acc[1] += xv * w4.y;
        acc[2] += xv * w4.z; acc[3] += xv * w4.w;
    }
    #pragma unroll
    for (int c = 0; c < 4; c++)
        acc[c] += __shfl_xor_sync(FULL, acc[c], 16);
}

// --------- warp matvec from GLOBAL weights, streaming (evict-first) ---------
__device__ __forceinline__ void warp_matvec_cs(const float* __restrict__ Wn,
                                               const float* xs, int lane, float acc[4]) {
    acc[0] = acc[1] = acc[2] = acc[3] = 0.f;
    int half = lane >> 4;
    int coff = (lane & 15) * 4;
    #pragma unroll
    for (int d = 0; d < DD; d += 2) {
        float4 w4 = __ldcs(reinterpret_cast<const float4*>(&Wn[(d + half) * DD + coff]));
        float xv = xs[d + half];
        acc[0] += xv * w4.x; acc[1] += xv * w4.y;
        acc[2] += xv * w4.z; acc[3] += xv * w4.w;
    }
    #pragma unroll
    for (int c = 0; c < 4; c++)
        acc[c] += __shfl_xor_sync(FULL, acc[c], 16);
}

// -------- combo: edge extraction + ELL placement AND conv1 lin (h1 = x @ Wc1) --------
// grid = 2500: block b handles edges [b*256, b*256+256) and nodes [b*8, b*8+8).
__global__ __launch_bounds__(256) void combo_kernel(const float* __restrict__ x,
                                                    const float* __restrict__ Wc,
                                                    const int* __restrict__ ei32,
                                                    const float* __restrict__ ew) {
    __shared__ float Ws[DD * DD];
    __shared__ float xs[8][DD];
    __shared__ int s_is64;
    int tid = threadIdx.x;

    // dtype probe (warp 0)
    if (tid < 32) {
        int ok = (ei32[2 * tid + 1] == 0) && (ei32[2 * (tid + 32) + 1] == 0);
        unsigned m = __ballot_sync(FULL, ok);
        if (tid == 0) s_is64 = (m == FULL);
    }

    // stage weights + node rows
    #pragma unroll
    for (int i = tid; i < DD * DD; i += 256) Ws[i] = Wc[i];
    int w = tid >> 5, lane = tid & 31;
    int node = blockIdx.x * 8 + w;
    *reinterpret_cast<float2*>(&xs[w][lane * 2]) =
        *reinterpret_cast<const float2*>(&x[(size_t)node * DD + lane * 2]);
    __syncthreads();

    // edge part: 1 edge/thread
    int is64 = s_is64;
    int e = blockIdx.x * 256 + tid;
    int s, d;
    if (is64) { s = __ldcs(&ei32[2 * e]); d = __ldcs(&ei32[2 * (EE + e)]); }
    else      { s = __ldcs(&ei32[e]);     d = __ldcs(&ei32[EE + e]); }
    float wgt = __ldcs(&ew[e]);
    atomicAdd(&g_deg[d], wgt);
    int rank = atomicAdd(&g_cnt[d], 1);
    g_ell[d * CAP + rank] = make_int2(s, __float_as_int(wgt));

    // matvec part (atomic latency drains underneath)
    float acc[4];
    warp_matvec_s(Ws, xs[w], lane, acc);
    if (lane < 16) {
        float4 o = make_float4(acc[0], acc[1], acc[2], acc[3]);
        *reinterpret_cast<float4*>(&g_h1[(size_t)node * DD + (lane & 15) * 4]) = o;
    }
}

// ---------------- conv2 fused: gather(h1, fold dinv_s) -> selu(+bc1) -> @Wc2 -> h2 ----------------
__global__ __launch_bounds__(256, 4) void conv2_fused_kernel(const float* __restrict__ Wc,
                                                             const float* __restrict__ bin) {
    __shared__ float Ws[DD * DD];
    __shared__ float xs[8][DD];
    int tid = threadIdx.x;
    #pragma unroll
    for (int i = tid; i < DD * DD; i += 256) Ws[i] = Wc[i];
    int w = tid >> 5, lane = tid & 31;
    int node = blockIdx.x * 8 + w;
    int coff = (lane & 15) * 4;
    float4 a = gather4<true>(g_h1, node, lane);
    if (lane < 16) {
        float4 bi = *reinterpret_cast<const float4*>(&bin[coff]);
        float4 sv = make_float4(selu_f(a.x + bi.x), selu_f(a.y + bi.y),
                                selu_f(a.z + bi.z), selu_f(a.w + bi.w));
        *reinterpret_cast<float4*>(&xs[w][coff]) = sv;
    }
    __syncthreads();
    float acc[4];
    warp_matvec_s(Ws, xs[w], lane, acc);
    if (lane < 16) {
        float4 o = make_float4(acc[0], acc[1], acc[2], acc[3]);
        *reinterpret_cast<float4*>(&g_h2[(size_t)node * DD + coff]) = o;
    }
}

// ------- final fused: gather(h2) -> selu(+bc2) -> W1 -> LN -> W2 -> out; restore state -------
__global__ __launch_bounds__(256, 4) void final_fused_kernel(
        const float* __restrict__ bc2,
        const float* __restrict__ W1, const float* __restrict__ b1,
        const float* __restrict__ W2, const float* __restrict__ b2,
        const float* __restrict__ gam, const float* __restrict__ bet,
        float* __restrict__ out) {
    __shared__ float hs[8][DD];
    __shared__ float ts[8][DD];
    int tid = threadIdx.x;
    int w = tid >> 5, lane = tid & 31;
    int node = blockIdx.x * 8 + w;
    int coff = (lane & 15) * 4;

    float4 a = gather4<false>(g_h2, node, lane);
    // last use of g_cnt/g_deg (own node only in this kernel): restore zeros for next replay
    if (lane == 0) { g_cnt[node] = 0; g_deg[node] = 0.f; }
    if (lane < 16) {
        float4 bi = *reinterpret_cast<const float4*>(&bc2[coff]);
        float4 sv = make_float4(selu_f(a.x + bi.x), selu_f(a.y + bi.y),
                                selu_f(a.z + bi.z), selu_f(a.w + bi.w));
        *reinterpret_cast<float4*>(&hs[w][coff]) = sv;
    }
    __syncwarp();

    const float* W1n = W1 + (size_t)node * (DD * DD);
    float v[4];
    warp_matvec_cs(W1n, hs[w], lane, v);
    float4 b1v = __ldcs(reinterpret_cast<const float4*>(&b1[(size_t)node * DD + coff]));
    v[0] += b1v.x; v[1] += b1v.y; v[2] += b1v.z; v[3] += b1v.w;

    // layernorm: each 16-lane half holds all 64 values (4 per lane)
    float s1 = v[0] + v[1] + v[2] + v[3];
    float s2 = v[0] * v[0] + v[1] * v[1] + v[2] * v[2] + v[3] * v[3];
    #pragma unroll
    for (int o = 8; o; o >>= 1) {
        s1 += __shfl_xor_sync(FULL, s1, o);
        s2 += __shfl_xor_sync(FULL, s2, o);
    }
    float mu  = s1 * (1.f / DD);
    float var = s2 * (1.f / DD) - mu * mu;
    float rstd = rsqrtf(var + 1e-5f);
    float4 gv = *reinterpret_cast<const float4*>(&gam[coff]);
    float4 bv = *reinterpret_cast<const float4*>(&bet[coff]);
    float t0 = (v[0] - mu) * rstd * gv.x + bv.x;
    float t1 = (v[1] - mu) * rstd * gv.y + bv.y;
    float t2 = (v[2] - mu) * rstd * gv.z + bv.z;
    float t3 = (v[3] - mu) * rstd * gv.w + bv.w;
    if (lane < 16)
        *reinterpret_cast<float4*>(&ts[w][coff]) = make_float4(t0, t1, t2, t3);
    __syncwarp();

    const float* W2n = W2 + (size_t)node * (DD * DD);
    float q[4];
    warp_matvec_cs(W2n, ts[w], lane, q);
    if (lane < 16) {
        float4 b2v = __ldcs(reinterpret_cast<const float4*>(&b2[(size_t)node * DD + coff]));
        float4 o = make_float4(q[0] + b2v.x, q[1] + b2v.y, q[2] + b2v.z, q[3] + b2v.w);
        *reinterpret_cast<float4*>(&out[(size_t)node * DD + coff]) = o;
    }
}

// ---------------- launch: 3 kernels, no streams/events ----------------
extern "C" void kernel_launch(void* const* d_in, const int* in_sizes, int n_in,
                              void* d_out, int out_size) {
    const float* x   = (const float*)d_in[0];
    const int*   ei  = (const int*)d_in[1];
    const float* ew  = (const float*)d_in[2];
    const float* Wc1 = (const float*)d_in[3];
    const float* bc1 = (const float*)d_in[4];
    const float* Wc2 = (const float*)d_in[5];
    const float* bc2 = (const float*)d_in[6];
    const float* W1  = (const float*)d_in[7];
    const float* b1  = (const float*)d_in[8];
    const float* W2  = (const float*)d_in[9];
    const float* b2  = (const float*)d_in[10];
    const float* gam = (const float*)d_in[11];
    const float* bet = (const float*)d_in[12];
    float* out = (float*)d_out;

    combo_kernel<<<EE / 256, 256>>>(x, Wc1, ei, ew);                       // edges + conv1 lin
    conv2_fused_kernel<<<NN / 8, 256>>>(Wc2, bc1);                         // gather+selu+lin
    final_fused_kernel<<<NN / 8, 256>>>(bc2, W1, b1, W2, b2, gam, bet, out);
}

// round 14
// speedup vs baseline: 1.6059x; 1.0206x over previous
#include <cuda_runtime.h>
#include <cuda_fp16.h>
#include <math.h>

#define NN 20000
#define EE 640000
#define DD 64
#define CAP 128          // ELL capacity per dst node (mean in-degree 32; P(>128) ~ 0)
#define FULL 0xffffffffu

// ---------------- scratch ----------------
// g_cnt / g_deg are zero at every kernel_launch entry: statically zero-initialized,
// and final_fused_kernel re-zeroes them after their last (own-node) use each invocation.
__device__ __align__(16) float  g_deg[NN];
__device__ __align__(16) int    g_cnt[NN];
__device__ __align__(16) int2   g_ell[NN * CAP]; // (src, weight-bits); conv2 folds dinv[src] in place
__device__ __align__(16) __half g_h1[NN * DD];   // fp16 storage, fp32 math
__device__ __align__(16) __half g_h2[NN * DD];

__device__ __forceinline__ float selu_f(float x) {
    const float sc = 1.0507009873554805f;
    const float al = 1.6732632423543772f;
    return x > 0.f ? sc * x : sc * al * (expf(x) - 1.f);
}

// ---- fp16x4 load/store helpers (8 bytes) ----
__device__ __forceinline__ float4 ld_h4(const __half* p) {
    uint2 u = *reinterpret_cast<const uint2*>(p);
    __half2 a = *reinterpret_cast<__half2*>(&u.x);
    __half2 b = *reinterpret_cast<__half2*>(&u.y);
    float2 fa = __half22float2(a), fb = __half22float2(b);
    return make_float4(fa.x, fa.y, fb.x, fb.y);
}
__device__ __forceinline__ void st_h4(__half* p, float4 v) {
    uint2 u;
    __half2 a = __floats2half2_rn(v.x, v.y);
    __half2 b = __floats2half2_rn(v.z, v.w);
    u.x = *reinterpret_cast<unsigned*>(&a);
    u.y = *reinterpret_cast<unsigned*>(&b);
    *reinterpret_cast<uint2*>(p) = u;
}

// ------- split-half ELL gather, 16 edges/iter (8 per half), fp16x4/lane. -------
// FOLD=true: ELL weight is raw ew; fold dinv[src] on the fly and write back.
// Returns dinv_n * sum + dinv_n^2 * h[n].
template <bool FOLD>
__device__ __forceinline__ float4 gather4(const __half* __restrict__ hsrc,
                                          int n, int lane) {
    int cnt_all = g_cnt[n];
    int2* row = &g_ell[(size_t)n * CAP];
    int half_ = lane >> 4;
    int coff = (lane & 15) * 4;
    float dinv_n = rsqrtf(1.f + g_deg[n]);
    float4 hv = ld_h4(&hsrc[(size_t)n * DD + coff]);
    float a0 = 0.f, a1 = 0.f, a2 = 0.f, a3 = 0.f;
    for (int base = 0; base < cnt_all; base += 32) {
        int idx = base + lane;
        int sx = 0, wb = 0;
        if (idx < cnt_all) {
            int2 ed = row[idx];
            sx = ed.x;
            if (FOLD) {
                float wn = __int_as_float(ed.y) * rsqrtf(1.f + g_deg[sx]);
                wb = __float_as_int(wn);
                row[idx].y = wb;   // fold once; final gather reuses
            } else {
                wb = ed.y;
            }
        }
        int cnt = min(32, cnt_all - base);
        for (int k = 0; k < cnt; k += 16) {  // OOB shfl sources carry (0,0): harmless
            int   s0 = __shfl_sync(FULL, sx, k + half_);
            float w0 = __int_as_float(__shfl_sync(FULL, wb, k + half_));
            int   s1 = __shfl_sync(FULL, sx, k + 2 + half_);
            float w1 = __int_as_float(__shfl_sync(FULL, wb, k + 2 + half_));
            int   s2 = __shfl_sync(FULL, sx, k + 4 + half_);
            float w2 = __int_as_float(__shfl_sync(FULL, wb, k + 4 + half_));
            int   s3 = __shfl_sync(FULL, sx, k + 6 + half_);
            float w3 = __int_as_float(__shfl_sync(FULL, wb, k + 6 + half_));
            int   s4 = __shfl_sync(FULL, sx, k + 8 + half_);
            float w4 = __int_as_float(__shfl_sync(FULL, wb, k + 8 + half_));
            int   s5 = __shfl_sync(FULL, sx, k + 10 + half_);
            float w5 = __int_as_float(__shfl_sync(FULL, wb, k + 10 + half_));
            int   s6 = __shfl_sync(FULL, sx, k + 12 + half_);
            float w6 = __int_as_float(__shfl_sync(FULL, wb, k + 12 + half_));
            int   s7 = __shfl_sync(FULL, sx, k + 14 + half_);
            float w7 = __int_as_float(__shfl_sync(FULL, wb, k + 14 + half_));
            float4 v0 = ld_h4(&hsrc[(size_t)s0 * DD + coff]);
            float4 v1 = ld_h4(&hsrc[(size_t)s1 * DD + coff]);
            float4 v2 = ld_h4(&hsrc[(size_t)s2 * DD + coff]);
            float4 v3 = ld_h4(&hsrc[(size_t)s3 * DD + coff]);
            float4 v4 = ld_h4(&hsrc[(size_t)s4 * DD + coff]);
            float4 v5 = ld_h4(&hsrc[(size_t)s5 * DD + coff]);
            float4 v6 = ld_h4(&hsrc[(size_t)s6 * DD + coff]);
            float4 v7 = ld_h4(&hsrc[(size_t)s7 * DD + coff]);
            a0 += w0 * v0.x + w1 * v1.x;  a1 += w0 * v0.y + w1 * v1.y;
            a2 += w0 * v0.z + w1 * v1.z;  a3 += w0 * v0.w + w1 * v1.w;
            a0 += w2 * v2.x + w3 * v3.x;  a1 += w2 * v2.y + w3 * v3.y;
            a2 += w2 * v2.z + w3 * v3.z;  a3 += w2 * v2.w + w3 * v3.w;
            a0 += w4 * v4.x + w5 * v5.x;  a1 += w4 * v4.y + w5 * v5.y;
            a2 += w4 * v4.z + w5 * v5.z;  a3 += w4 * v4.w + w5 * v5.w;
            a0 += w6 * v6.x + w7 * v7.x;  a1 += w6 * v6.y + w7 * v7.y;
            a2 += w6 * v6.z + w7 * v7.z;  a3 += w6 * v6.w + w7 * v7.w;
        }
    }
    a0 += __shfl_xor_sync(FULL, a0, 16);
    a1 += __shfl_xor_sync(FULL, a1, 16);
    a2 += __shfl_xor_sync(FULL, a2, 16);
    a3 += __shfl_xor_sync(FULL, a3, 16);
    float self = dinv_n * dinv_n;
    return make_float4(dinv_n * a0 + hv.x * self, dinv_n * a1 + hv.y * self,
                       dinv_n * a2 + hv.z * self, dinv_n * a3 + hv.w * self);
}

// --------- warp matvec from SMEM weights ---------
__device__ __forceinline__ void warp_matvec_s(const float* Wn,
                                              const float* xs, int lane, float acc[4]) {
    acc[0] = acc[1] = acc[2] = acc[3] = 0.f;
    int half_ = lane >> 4;
    int coff = (lane & 15) * 4;
    #pragma unroll
    for (int d = 0; d < DD; d += 2) {
        float4 w4 = *reinterpret_cast<const float4*>(&Wn[(d + half_) * DD + coff]);
        float xv = xs[d + half_];
        acc[0] += xv * w4.x; acc[1] += xv * w4.y;
        acc[2] += xv * w4.z; acc[3] += xv * w4.w;
    }
    #pragma unroll
    for (int c = 0; c < 4; c++)
        acc[c] += __shfl_xor_sync(FULL, acc[c], 16);
}

// --------- warp matvec from GLOBAL weights, streaming (evict-first) ---------
__device__ __forceinline__ void warp_matvec_cs(const float* __restrict__ Wn,
                                               const float* xs, int lane, float acc[4]) {
    acc[0] = acc[1] = acc[2] = acc[3] = 0.f;
    int half_ = lane >> 4;
    int coff = (lane & 15) * 4;
    #pragma unroll
    for (int d = 0; d < DD; d += 2) {
        float4 w4 = __ldcs(reinterpret_cast<const float4*>(&Wn[(d + half_) * DD + coff]));
        float xv = xs[d + half_];
        acc[0] += xv * w4.x; acc[1] += xv * w4.y;
        acc[2] += xv * w4.z; acc[3] += xv * w4.w;
    }
    #pragma unroll
    for (int c = 0; c < 4; c++)
        acc[c] += __shfl_xor_sync(FULL, acc[c], 16);
}

// -------- combo: edge extraction + ELL placement AND conv1 lin (h1 = x @ Wc1) --------
__global__ __launch_bounds__(256) void combo_kernel(const float* __restrict__ x,
                                                    const float* __restrict__ Wc,
                                                    const int* __restrict__ ei32,
                                                    const float* __restrict__ ew) {
    __shared__ float Ws[DD * DD];
    __shared__ float xs[8][DD];
    __shared__ int s_is64;
    int tid = threadIdx.x;

    if (tid < 32) {
        int ok = (ei32[2 * tid + 1] == 0) && (ei32[2 * (tid + 32) + 1] == 0);
        unsigned m = __ballot_sync(FULL, ok);
        if (tid == 0) s_is64 = (m == FULL);
    }

    #pragma unroll
    for (int i = tid; i < DD * DD; i += 256) Ws[i] = Wc[i];
    int w = tid >> 5, lane = tid & 31;
    int node = blockIdx.x * 8 + w;
    *reinterpret_cast<float2*>(&xs[w][lane * 2]) =
        *reinterpret_cast<const float2*>(&x[(size_t)node * DD + lane * 2]);
    __syncthreads();

    int is64 = s_is64;
    int e = blockIdx.x * 256 + tid;
    int s, d;
    if (is64) { s = __ldcs(&ei32[2 * e]); d = __ldcs(&ei32[2 * (EE + e)]); }
    else      { s = __ldcs(&ei32[e]);     d = __ldcs(&ei32[EE + e]); }
    float wgt = __ldcs(&ew[e]);
    atomicAdd(&g_deg[d], wgt);
    int rank = atomicAdd(&g_cnt[d], 1);
    g_ell[d * CAP + rank] = make_int2(s, __float_as_int(wgt));

    float acc[4];
    warp_matvec_s(Ws, xs[w], lane, acc);
    if (lane < 16)
        st_h4(&g_h1[(size_t)node * DD + (lane & 15) * 4],
              make_float4(acc[0], acc[1], acc[2], acc[3]));
}

// ---------------- conv2 fused: gather(h1, fold dinv_s) -> selu(+bc1) -> @Wc2 -> h2 ----------------
__global__ __launch_bounds__(256, 4) void conv2_fused_kernel(const float* __restrict__ Wc,
                                                             const float* __restrict__ bin) {
    __shared__ float Ws[DD * DD];
    __shared__ float xs[8][DD];
    int tid = threadIdx.x;
    #pragma unroll
    for (int i = tid; i < DD * DD; i += 256) Ws[i] = Wc[i];
    int w = tid >> 5, lane = tid & 31;
    int node = blockIdx.x * 8 + w;
    int coff = (lane & 15) * 4;
    float4 a = gather4<true>(g_h1, node, lane);
    if (lane < 16) {
        float4 bi = *reinterpret_cast<const float4*>(&bin[coff]);
        float4 sv = make_float4(selu_f(a.x + bi.x), selu_f(a.y + bi.y),
                                selu_f(a.z + bi.z), selu_f(a.w + bi.w));
        *reinterpret_cast<float4*>(&xs[w][coff]) = sv;
    }
    __syncthreads();
    float acc[4];
    warp_matvec_s(Ws, xs[w], lane, acc);
    if (lane < 16)
        st_h4(&g_h2[(size_t)node * DD + coff],
              make_float4(acc[0], acc[1], acc[2], acc[3]));
}

// ------- final fused: gather(h2) -> selu(+bc2) -> W1 -> LN -> W2 -> out; restore state -------
__global__ __launch_bounds__(256, 4) void final_fused_kernel(
        const float* __restrict__ bc2,
        const float* __restrict__ W1, const float* __restrict__ b1,
        const float* __restrict__ W2, const float* __restrict__ b2,
        const float* __restrict__ gam, const float* __restrict__ bet,
        float* __restrict__ out) {
    __shared__ float hs[8][DD];
    __shared__ float ts[8][DD];
    int tid = threadIdx.x;
    int w = tid >> 5, lane = tid & 31;
    int node = blockIdx.x * 8 + w;
    int coff = (lane & 15) * 4;

    float4 a = gather4<false>(g_h2, node, lane);
    // last use of g_cnt/g_deg (own node only in this kernel): restore zeros for next replay
    if (lane == 0) { g_cnt[node] = 0; g_deg[node] = 0.f; }
    if (lane < 16) {
        float4 bi = *reinterpret_cast<const float4*>(&bc2[coff]);
        float4 sv = make_float4(selu_f(a.x + bi.x), selu_f(a.y + bi.y),
                                selu_f(a.z + bi.z), selu_f(a.w + bi.w));
        *reinterpret_cast<float4*>(&hs[w][coff]) = sv;
    }
    __syncwarp();

    const float* W1n = W1 + (size_t)node * (DD * DD);
    float v[4];
    warp_matvec_cs(W1n, hs[w], lane, v);
    float4 b1v = __ldcs(reinterpret_cast<const float4*>(&b1[(size_t)node * DD + coff]));
    v[0] += b1v.x; v[1] += b1v.y; v[2] += b1v.z; v[3] += b1v.w;

    // layernorm: each 16-lane half holds all 64 values (4 per lane)
    float s1 = v[0] + v[1] + v[2] + v[3];
    float s2 = v[0] * v[0] + v[1] * v[1] + v[2] * v[2] + v[3] * v[3];
    #pragma unroll
    for (int o = 8; o; o >>= 1) {
        s1 += __shfl_xor_sync(FULL, s1, o);
        s2 += __shfl_xor_sync(FULL, s2, o);
    }
    float mu  = s1 * (1.f / DD);
    float var = s2 * (1.f / DD) - mu * mu;
    float rstd = rsqrtf(var + 1e-5f);
    float4 gv = *reinterpret_cast<const float4*>(&gam[coff]);
    float4 bv = *reinterpret_cast<const float4*>(&bet[coff]);
    float t0 = (v[0] - mu) * rstd * gv.x + bv.x;
    float t1 = (v[1] - mu) * rstd * gv.y + bv.y;
    float t2 = (v[2] - mu) * rstd * gv.z + bv.z;
    float t3 = (v[3] - mu) * rstd * gv.w + bv.w;
    if (lane < 16)
        *reinterpret_cast<float4*>(&ts[w][coff]) = make_float4(t0, t1, t2, t3);
    __syncwarp();

    const float* W2n = W2 + (size_t)node * (DD * DD);
    float q[4];
    warp_matvec_cs(W2n, ts[w], lane, q);
    if (lane < 16) {
        float4 b2v = __ldcs(reinterpret_cast<const float4*>(&b2[(size_t)node * DD + coff]));
        float4 o = make_float4(q[0] + b2v.x, q[1] + b2v.y, q[2] + b2v.z, q[3] + b2v.w);
        *reinterpret_cast<float4*>(&out[(size_t)node * DD + coff]) = o;
    }
}

// ---------------- launch: 3 kernels ----------------
extern "C" void kernel_launch(void* const* d_in, const int* in_sizes, int n_in,
                              void* d_out, int out_size) {
    const float* x   = (const float*)d_in[0];
    const int*   ei  = (const int*)d_in[1];
    const float* ew  = (const float*)d_in[2];
    const float* Wc1 = (const float*)d_in[3];
    const float* bc1 = (const float*)d_in[4];
    const float* Wc2 = (const float*)d_in[5];
    const float* bc2 = (const float*)d_in[6];
    const float* W1  = (const float*)d_in[7];
    const float* b1  = (const float*)d_in[8];
    const float* W2  = (const float*)d_in[9];
    const float* b2  = (const float*)d_in[10];
    const float* gam = (const float*)d_in[11];
    const float* bet = (const float*)d_in[12];
    float* out = (float*)d_out;

    combo_kernel<<<EE / 256, 256>>>(x, Wc1, ei, ew);
    conv2_fused_kernel<<<NN / 8, 256>>>(Wc2, bc1);
    final_fused_kernel<<<NN / 8, 256>>>(bc2, W1, b1, W2, b2, gam, bet, out);
}

// round 15
// speedup vs baseline: 1.6233x; 1.0108x over previous
#include <cuda_runtime.h>
#include <cuda_fp16.h>
#include <math.h>

#define NN 20000
#define EE 640000
#define DD 64
#define CAP 128          // ELL capacity per dst node (mean in-degree 32; P(>128) ~ 0)
#define FULL 0xffffffffu
#define FXS 16777216.0f  // 2^24 fixed-point scale for packed degree

// ---------------- scratch ----------------
// g_pack is zero at every kernel_launch entry: statically zero-initialized,
// and final_fused_kernel re-zeroes it after its last (own-node) use each invocation.
// layout: [63:32] = in-count, [31:0] = sum(ew) in 2^-24 fixed point (max 2^31, no carry).
__device__ __align__(16) unsigned long long g_pack[NN];
__device__ __align__(16) int2   g_ell[NN * CAP]; // (src, weight-bits); conv2 folds dinv[src] in place
__device__ __align__(16) __half g_h1[NN * DD];   // fp16 storage, fp32 math
__device__ __align__(16) __half g_h2[NN * DD];

__device__ __forceinline__ float selu_f(float x) {
    const float sc = 1.0507009873554805f;
    const float al = 1.6732632423543772f;
    return x > 0.f ? sc * x : sc * al * (expf(x) - 1.f);
}

__device__ __forceinline__ void decode_pack(unsigned long long p, int& cnt, float& deg) {
    cnt = (int)(p >> 32);
    deg = (float)(unsigned)(p & 0xffffffffULL) * (1.0f / FXS);
}

// ---- fp16x4 load/store helpers (8 bytes) ----
__device__ __forceinline__ float4 ld_h4(const __half* p) {
    uint2 u = *reinterpret_cast<const uint2*>(p);
    __half2 a = *reinterpret_cast<__half2*>(&u.x);
    __half2 b = *reinterpret_cast<__half2*>(&u.y);
    float2 fa = __half22float2(a), fb = __half22float2(b);
    return make_float4(fa.x, fa.y, fb.x, fb.y);
}
__device__ __forceinline__ void st_h4(__half* p, float4 v) {
    uint2 u;
    __half2 a = __floats2half2_rn(v.x, v.y);
    __half2 b = __floats2half2_rn(v.z, v.w);
    u.x = *reinterpret_cast<unsigned*>(&a);
    u.y = *reinterpret_cast<unsigned*>(&b);
    *reinterpret_cast<uint2*>(p) = u;
}

// ------- split-half ELL gather, 16 edges/iter (8 per half), fp16x4/lane. -------
// FOLD=true: ELL weight is raw ew; fold dinv[src] on the fly and write back.
// Returns dinv_n * sum + dinv_n^2 * h[n].
template <bool FOLD>
__device__ __forceinline__ float4 gather4(const __half* __restrict__ hsrc,
                                          int n, int lane) {
    int cnt_all; float deg_n;
    decode_pack(g_pack[n], cnt_all, deg_n);
    int2* row = &g_ell[(size_t)n * CAP];
    int half_ = lane >> 4;
    int coff = (lane & 15) * 4;
    float dinv_n = rsqrtf(1.f + deg_n);
    float4 hv = ld_h4(&hsrc[(size_t)n * DD + coff]);
    float a0 = 0.f, a1 = 0.f, a2 = 0.f, a3 = 0.f;
    for (int base = 0; base < cnt_all; base += 32) {
        int idx = base + lane;
        int sx = 0, wb = 0;
        if (idx < cnt_all) {
            int2 ed = row[idx];
            sx = ed.x;
            if (FOLD) {
                int c_s; float deg_s;
                decode_pack(g_pack[sx], c_s, deg_s);
                float wn = __int_as_float(ed.y) * rsqrtf(1.f + deg_s);
                wb = __float_as_int(wn);
                row[idx].y = wb;   // fold once; final gather reuses
            } else {
                wb = ed.y;
            }
        }
        int cnt = min(32, cnt_all - base);
        for (int k = 0; k < cnt; k += 16) {  // OOB shfl sources carry (0,0): harmless
            int   s0 = __shfl_sync(FULL, sx, k + half_);
            float w0 = __int_as_float(__shfl_sync(FULL, wb, k + half_));
            int   s1 = __shfl_sync(FULL, sx, k + 2 + half_);
            float w1 = __int_as_float(__shfl_sync(FULL, wb, k + 2 + half_));
            int   s2 = __shfl_sync(FULL, sx, k + 4 + half_);
            float w2 = __int_as_float(__shfl_sync(FULL, wb, k + 4 + half_));
            int   s3 = __shfl_sync(FULL, sx, k + 6 + half_);
            float w3 = __int_as_float(__shfl_sync(FULL, wb, k + 6 + half_));
            int   s4 = __shfl_sync(FULL, sx, k + 8 + half_);
            float w4 = __int_as_float(__shfl_sync(FULL, wb, k + 8 + half_));
            int   s5 = __shfl_sync(FULL, sx, k + 10 + half_);
            float w5 = __int_as_float(__shfl_sync(FULL, wb, k + 10 + half_));
            int   s6 = __shfl_sync(FULL, sx, k + 12 + half_);
            float w6 = __int_as_float(__shfl_sync(FULL, wb, k + 12 + half_));
            int   s7 = __shfl_sync(FULL, sx, k + 14 + half_);
            float w7 = __int_as_float(__shfl_sync(FULL, wb, k + 14 + half_));
            float4 v0 = ld_h4(&hsrc[(size_t)s0 * DD + coff]);
            float4 v1 = ld_h4(&hsrc[(size_t)s1 * DD + coff]);
            float4 v2 = ld_h4(&hsrc[(size_t)s2 * DD + coff]);
            float4 v3 = ld_h4(&hsrc[(size_t)s3 * DD + coff]);
            float4 v4 = ld_h4(&hsrc[(size_t)s4 * DD + coff]);
            float4 v5 = ld_h4(&hsrc[(size_t)s5 * DD + coff]);
            float4 v6 = ld_h4(&hsrc[(size_t)s6 * DD + coff]);
            float4 v7 = ld_h4(&hsrc[(size_t)s7 * DD + coff]);
            a0 += w0 * v0.x + w1 * v1.x;  a1 += w0 * v0.y + w1 * v1.y;
            a2 += w0 * v0.z + w1 * v1.z;  a3 += w0 * v0.w + w1 * v1.w;
            a0 += w2 * v2.x + w3 * v3.x;  a1 += w2 * v2.y + w3 * v3.y;
            a2 += w2 * v2.z + w3 * v3.z;  a3 += w2 * v2.w + w3 * v3.w;
            a0 += w4 * v4.x + w5 * v5.x;  a1 += w4 * v4.y + w5 * v5.y;
            a2 += w4 * v4.z + w5 * v5.z;  a3 += w4 * v4.w + w5 * v5.w;
            a0 += w6 * v6.x + w7 * v7.x;  a1 += w6 * v6.y + w7 * v7.y;
            a2 += w6 * v6.z + w7 * v7.z;  a3 += w6 * v6.w + w7 * v7.w;
        }
    }
    a0 += __shfl_xor_sync(FULL, a0, 16);
    a1 += __shfl_xor_sync(FULL, a1, 16);
    a2 += __shfl_xor_sync(FULL, a2, 16);
    a3 += __shfl_xor_sync(FULL, a3, 16);
    float self = dinv_n * dinv_n;
    return make_float4(dinv_n * a0 + hv.x * self, dinv_n * a1 + hv.y * self,
                       dinv_n * a2 + hv.z * self, dinv_n * a3 + hv.w * self);
}

// --------- warp matvec from SMEM weights ---------
__device__ __forceinline__ void warp_matvec_s(const float* Wn,
                                              const float* xs, int lane, float acc[4]) {
    acc[0] = acc[1] = acc[2] = acc[3] = 0.f;
    int half_ = lane >> 4;
    int coff = (lane & 15) * 4;
    #pragma unroll
    for (int d = 0; d < DD; d += 2) {
        float4 w4 = *reinterpret_cast<const float4*>(&Wn[(d + half_) * DD + coff]);
        float xv = xs[d + half_];
        acc[0] += xv * w4.x; acc[1] += xv * w4.y;
        acc[2] += xv * w4.z; acc[3] += xv * w4.w;
    }
    #pragma unroll
    for (int c = 0; c < 4; c++)
        acc[c] += __shfl_xor_sync(FULL, acc[c], 16);
}

// --------- warp matvec from GLOBAL weights, streaming (evict-first) ---------
__device__ __forceinline__ void warp_matvec_cs(const float* __restrict__ Wn,
                                               const float* xs, int lane, float acc[4]) {
    acc[0] = acc[1] = acc[2] = acc[3] = 0.f;
    int half_ = lane >> 4;
    int coff = (lane & 15) * 4;
    #pragma unroll
    for (int d = 0; d < DD; d += 2) {
        float4 w4 = __ldcs(reinterpret_cast<const float4*>(&Wn[(d + half_) * DD + coff]));
        float xv = xs[d + half_];
        acc[0] += xv * w4.x; acc[1] += xv * w4.y;
        acc[2] += xv * w4.z; acc[3] += xv * w4.w;
    }
    #pragma unroll
    for (int c = 0; c < 4; c++)
        acc[c] += __shfl_xor_sync(FULL, acc[c], 16);
}

// -------- combo: edge extraction + ELL placement AND conv1 lin (h1 = x @ Wc1) --------
__global__ __launch_bounds__(256) void combo_kernel(const float* __restrict__ x,
                                                    const float* __restrict__ Wc,
                                                    const int* __restrict__ ei32,
                                                    const float* __restrict__ ew) {
    __shared__ float Ws[DD * DD];
    __shared__ float xs[8][DD];
    __shared__ int s_is64;
    int tid = threadIdx.x;

    if (tid < 32) {
        int ok = (ei32[2 * tid + 1] == 0) && (ei32[2 * (tid + 32) + 1] == 0);
        unsigned m = __ballot_sync(FULL, ok);
        if (tid == 0) s_is64 = (m == FULL);
    }

    #pragma unroll
    for (int i = tid; i < DD * DD; i += 256) Ws[i] = Wc[i];
    int w = tid >> 5, lane = tid & 31;
    int node = blockIdx.x * 8 + w;
    *reinterpret_cast<float2*>(&xs[w][lane * 2]) =
        *reinterpret_cast<const float2*>(&x[(size_t)node * DD + lane * 2]);
    __syncthreads();

    int is64 = s_is64;
    int e = blockIdx.x * 256 + tid;
    int s, d;
    if (is64) { s = __ldcs(&ei32[2 * e]); d = __ldcs(&ei32[2 * (EE + e)]); }
    else      { s = __ldcs(&ei32[e]);     d = __ldcs(&ei32[EE + e]); }
    float wgt = __ldcs(&ew[e]);
    // single packed atomic: count in high 32, fixed-point degree in low 32
    unsigned fx = (unsigned)__float2uint_rn(wgt * FXS);
    unsigned long long old =
        atomicAdd(&g_pack[d], (1ULL << 32) | (unsigned long long)fx);
    int rank = (int)(old >> 32);
    g_ell[d * CAP + rank] = make_int2(s, __float_as_int(wgt));

    float acc[4];
    warp_matvec_s(Ws, xs[w], lane, acc);
    if (lane < 16)
        st_h4(&g_h1[(size_t)node * DD + (lane & 15) * 4],
              make_float4(acc[0], acc[1], acc[2], acc[3]));
}

// ---------------- conv2 fused: gather(h1, fold dinv_s) -> selu(+bc1) -> @Wc2 -> h2 ----------------
__global__ __launch_bounds__(256, 4) void conv2_fused_kernel(const float* __restrict__ Wc,
                                                             const float* __restrict__ bin) {
    __shared__ float Ws[DD * DD];
    __shared__ float xs[8][DD];
    int tid = threadIdx.x;
    #pragma unroll
    for (int i = tid; i < DD * DD; i += 256) Ws[i] = Wc[i];
    int w = tid >> 5, lane = tid & 31;
    int node = blockIdx.x * 8 + w;
    int coff = (lane & 15) * 4;
    float4 a = gather4<true>(g_h1, node, lane);
    if (lane < 16) {
        float4 bi = *reinterpret_cast<const float4*>(&bin[coff]);
        float4 sv = make_float4(selu_f(a.x + bi.x), selu_f(a.y + bi.y),
                                selu_f(a.z + bi.z), selu_f(a.w + bi.w));
        *reinterpret_cast<float4*>(&xs[w][coff]) = sv;
    }
    __syncthreads();
    float acc[4];
    warp_matvec_s(Ws, xs[w], lane, acc);
    if (lane < 16)
        st_h4(&g_h2[(size_t)node * DD + coff],
              make_float4(acc[0], acc[1], acc[2], acc[3]));
}

// ------- final fused: gather(h2) -> selu(+bc2) -> W1 -> LN -> W2 -> out; restore state -------
__global__ __launch_bounds__(256, 4) void final_fused_kernel(
        const float* __restrict__ bc2,
        const float* __restrict__ W1, const float* __restrict__ b1,
        const float* __restrict__ W2, const float* __restrict__ b2,
        const float* __restrict__ gam, const float* __restrict__ bet,
        float* __restrict__ out) {
    __shared__ float hs[8][DD];
    __shared__ float ts[8][DD];
    int tid = threadIdx.x;
    int w = tid >> 5, lane = tid & 31;
    int node = blockIdx.x * 8 + w;
    int coff = (lane & 15) * 4;

    float4 a = gather4<false>(g_h2, node, lane);
    // last use of g_pack (own node only in this kernel): restore zero for next replay
    if (lane == 0) g_pack[node] = 0ULL;
    if (lane < 16) {
        float4 bi = *reinterpret_cast<const float4*>(&bc2[coff]);
        float4 sv = make_float4(selu_f(a.x + bi.x), selu_f(a.y + bi.y),
                                selu_f(a.z + bi.z), selu_f(a.w + bi.w));
        *reinterpret_cast<float4*>(&hs[w][coff]) = sv;
    }
    __syncwarp();

    const float* W1n = W1 + (size_t)node * (DD * DD);
    float v[4];
    warp_matvec_cs(W1n, hs[w], lane, v);
    float4 b1v = __ldcs(reinterpret_cast<const float4*>(&b1[(size_t)node * DD + coff]));
    v[0] += b1v.x; v[1] += b1v.y; v[2] += b1v.z; v[3] += b1v.w;

    // layernorm: each 16-lane half holds all 64 values (4 per lane)
    float s1 = v[0] + v[1] + v[2] + v[3];
    float s2 = v[0] * v[0] + v[1] * v[1] + v[2] * v[2] + v[3] * v[3];
    #pragma unroll
    for (int o = 8; o; o >>= 1) {
        s1 += __shfl_xor_sync(FULL, s1, o);
        s2 += __shfl_xor_sync(FULL, s2, o);
    }
    float mu  = s1 * (1.f / DD);
    float var = s2 * (1.f / DD) - mu * mu;
    float rstd = rsqrtf(var + 1e-5f);
    float4 gv = *reinterpret_cast<const float4*>(&gam[coff]);
    float4 bv = *reinterpret_cast<const float4*>(&bet[coff]);
    float t0 = (v[0] - mu) * rstd * gv.x + bv.x;
    float t1 = (v[1] - mu) * rstd * gv.y + bv.y;
    float t2 = (v[2] - mu) * rstd * gv.z + bv.z;
    float t3 = (v[3] - mu) * rstd * gv.w + bv.w;
    if (lane < 16)
        *reinterpret_cast<float4*>(&ts[w][coff]) = make_float4(t0, t1, t2, t3);
    __syncwarp();

    const float* W2n = W2 + (size_t)node * (DD * DD);
    float q[4];
    warp_matvec_cs(W2n, ts[w], lane, q);
    if (lane < 16) {
        float4 b2v = __ldcs(reinterpret_cast<const float4*>(&b2[(size_t)node * DD + coff]));
        float4 o = make_float4(q[0] + b2v.x, q[1] + b2v.y, q[2] + b2v.z, q[3] + b2v.w);
        *reinterpret_cast<float4*>(&out[(size_t)node * DD + coff]) = o;
    }
}

// ---------------- launch: 3 kernels ----------------
extern "C" void kernel_launch(void* const* d_in, const int* in_sizes, int n_in,
                              void* d_out, int out_size) {
    const float* x   = (const float*)d_in[0];
    const int*   ei  = (const int*)d_in[1];
    const float* ew  = (const float*)d_in[2];
    const float* Wc1 = (const float*)d_in[3];
    const float* bc1 = (const float*)d_in[4];
    const float* Wc2 = (const float*)d_in[5];
    const float* bc2 = (const float*)d_in[6];
    const float* W1  = (const float*)d_in[7];
    const float* b1  = (const float*)d_in[8];
    const float* W2  = (const float*)d_in[9];
    const float* b2  = (const float*)d_in[10];
    const float* gam = (const float*)d_in[11];
    const float* bet = (const float*)d_in[12];
    float* out = (float*)d_out;

    combo_kernel<<<EE / 256, 256>>>(x, Wc1, ei, ew);
    conv2_fused_kernel<<<NN / 8, 256>>>(Wc2, bc1);
    final_fused_kernel<<<NN / 8, 256>>>(bc2, W1, b1, W2, b2, gam, bet, out);
}